// round 2
// baseline (speedup 1.0000x reference)
#include <cuda_runtime.h>

#define N_NODES 40000
#define N_EDGES 640000
#define ND 128
#define ED 64
#define IN_DIM 320   // 2*ND + ED
#define TE 8         // edges per block
#define TN 4         // nodes per block (GRU)

// Scratch accumulator for scatter-add (device global: no allocation).
__device__ float g_agg[(size_t)N_NODES * ND];

__global__ void zero_agg_kernel() {
    size_t total = (size_t)N_NODES * ND / 4;
    float4 z = make_float4(0.f, 0.f, 0.f, 0.f);
    for (size_t i = (size_t)blockIdx.x * blockDim.x + threadIdx.x; i < total;
         i += (size_t)gridDim.x * blockDim.x)
        ((float4*)g_agg)[i] = z;
}

__global__ __launch_bounds__(128) void edge_kernel(
    const float* __restrict__ nf, const int* __restrict__ ei,
    const float* __restrict__ ef, const float* __restrict__ W1,
    const float* __restrict__ b1, const float* __restrict__ ln_g,
    const float* __restrict__ ln_b, const float* __restrict__ W2,
    const float* __restrict__ b2, const float* __restrict__ gate_w,
    const float* __restrict__ gate_b)
{
    __shared__ __align__(16) float xs[TE][IN_DIM];  // gathered edge inputs
    __shared__ __align__(16) float hb[TE][ND];      // post-LN+ReLU hidden
    __shared__ float redS[TE][4], redQ[TE][4];      // per-warp LN partials
    __shared__ float gatev[TE];
    __shared__ int   dsts[TE];

    const int t = threadIdx.x;       // feature index 0..127
    const int warp = t >> 5, lane = t & 31;
    const int e0 = blockIdx.x * TE;

    // ---- Gather: each warp loads 2 edges (src row, dst row, edge feats) ----
    #pragma unroll
    for (int i = 0; i < 2; i++) {
        int el = warp * 2 + i;
        int e  = e0 + el;
        int s  = ei[e];
        int d  = ei[N_EDGES + e];
        if (lane == 0) dsts[el] = d;
        float4* xr = (float4*)xs[el];
        xr[lane]      = ((const float4*)(nf + (size_t)s * ND))[lane];
        xr[32 + lane] = ((const float4*)(nf + (size_t)d * ND))[lane];
        if (lane < 16)
            xr[64 + lane] = ((const float4*)(ef + (size_t)e * ED))[lane];
    }
    __syncthreads();

    // ---- Edge gate (8 threads, one per edge) from raw edge features ----
    if (t < TE) {
        float g = gate_b[0];
        #pragma unroll 8
        for (int k = 0; k < ED; k++) g += xs[t][2 * ND + k] * gate_w[k];
        gatev[t] = 1.0f / (1.0f + __expf(-g));
    }

    // ---- Layer 1: h[e][t] = b1[t] + x[e] . W1[:,t] ----
    float acc[TE];
    {
        float bias1 = b1[t];
        #pragma unroll
        for (int e = 0; e < TE; e++) acc[e] = bias1;
    }
    for (int k = 0; k < IN_DIM; k += 4) {
        float w0 = W1[(k + 0) * ND + t];
        float w1 = W1[(k + 1) * ND + t];
        float w2 = W1[(k + 2) * ND + t];
        float w3 = W1[(k + 3) * ND + t];
        #pragma unroll
        for (int e = 0; e < TE; e++) {
            float4 x = *(const float4*)&xs[e][k];
            acc[e] += x.x * w0 + x.y * w1 + x.z * w2 + x.w * w3;
        }
    }

    // ---- LayerNorm: reduce mean / mean-of-squares across 128 threads ----
    {
        float s_[TE], q_[TE];
        #pragma unroll
        for (int e = 0; e < TE; e++) { s_[e] = acc[e]; q_[e] = acc[e] * acc[e]; }
        #pragma unroll
        for (int off = 16; off > 0; off >>= 1) {
            #pragma unroll
            for (int e = 0; e < TE; e++) {
                s_[e] += __shfl_xor_sync(0xffffffff, s_[e], off);
                q_[e] += __shfl_xor_sync(0xffffffff, q_[e], off);
            }
        }
        if (lane == 0) {
            #pragma unroll
            for (int e = 0; e < TE; e++) { redS[e][warp] = s_[e]; redQ[e][warp] = q_[e]; }
        }
    }
    __syncthreads();
    {
        float g_ = ln_g[t], bb = ln_b[t];
        #pragma unroll
        for (int e = 0; e < TE; e++) {
            float s  = redS[e][0] + redS[e][1] + redS[e][2] + redS[e][3];
            float q  = redQ[e][0] + redQ[e][1] + redQ[e][2] + redQ[e][3];
            float mu = s * (1.0f / ND);
            float var = q * (1.0f / ND) - mu * mu;
            float inv = rsqrtf(var + 1e-5f);
            float h = (acc[e] - mu) * inv * g_ + bb;
            hb[e][t] = fmaxf(h, 0.0f);    // ReLU
        }
    }
    __syncthreads();

    // ---- Layer 2 + gate + scatter-add ----
    float acc2[TE];
    {
        float bias2 = b2[t];
        #pragma unroll
        for (int e = 0; e < TE; e++) acc2[e] = bias2;
    }
    for (int k = 0; k < ND; k += 4) {
        float w0 = W2[(k + 0) * ND + t];
        float w1 = W2[(k + 1) * ND + t];
        float w2 = W2[(k + 2) * ND + t];
        float w3 = W2[(k + 3) * ND + t];
        #pragma unroll
        for (int e = 0; e < TE; e++) {
            float4 h4 = *(const float4*)&hb[e][k];
            acc2[e] += h4.x * w0 + h4.y * w1 + h4.z * w2 + h4.w * w3;
        }
    }
    #pragma unroll
    for (int e = 0; e < TE; e++)
        atomicAdd(&g_agg[(size_t)dsts[e] * ND + t], acc2[e] * gatev[e]);
}

__device__ __forceinline__ float sigmoidf_(float x) {
    return 1.0f / (1.0f + __expf(-x));
}

__global__ __launch_bounds__(128) void gru_kernel(
    const float* __restrict__ nf, const float* __restrict__ W_ih,
    const float* __restrict__ b_ih, const float* __restrict__ W_hh,
    const float* __restrict__ b_hh, float* __restrict__ out)
{
    __shared__ __align__(16) float as[TN][ND];   // aggregated messages
    __shared__ __align__(16) float xsn[TN][ND];  // node hidden states

    const int t = threadIdx.x;
    const int n0 = blockIdx.x * TN;

    // Load TN rows of agg and node_features (128 threads = 128 float4 slots)
    {
        int n = t >> 5, j = t & 31;
        ((float4*)as[n])[j]  = ((const float4*)(g_agg + (size_t)(n0 + n) * ND))[j];
        ((float4*)xsn[n])[j] = ((const float4*)(nf + (size_t)(n0 + n) * ND))[j];
    }
    __syncthreads();

    float rv[TN], zv[TN], outv[TN];

    for (int g = 0; g < 3; g++) {   // torch gate order: r, z, n
        float gi[TN], gh[TN];
        float bi = b_ih[g * ND + t], bh = b_hh[g * ND + t];
        #pragma unroll
        for (int n = 0; n < TN; n++) { gi[n] = bi; gh[n] = bh; }
        const float4* wi = (const float4*)(W_ih + (size_t)(g * ND + t) * ND);
        const float4* wh = (const float4*)(W_hh + (size_t)(g * ND + t) * ND);
        for (int k4 = 0; k4 < ND / 4; k4++) {
            float4 wiv = wi[k4], whv = wh[k4];
            #pragma unroll
            for (int n = 0; n < TN; n++) {
                float4 a4 = ((const float4*)as[n])[k4];
                float4 x4 = ((const float4*)xsn[n])[k4];
                gi[n] += a4.x * wiv.x + a4.y * wiv.y + a4.z * wiv.z + a4.w * wiv.w;
                gh[n] += x4.x * whv.x + x4.y * whv.y + x4.z * whv.z + x4.w * whv.w;
            }
        }
        if (g == 0) {
            #pragma unroll
            for (int n = 0; n < TN; n++) rv[n] = sigmoidf_(gi[n] + gh[n]);
        } else if (g == 1) {
            #pragma unroll
            for (int n = 0; n < TN; n++) zv[n] = sigmoidf_(gi[n] + gh[n]);
        } else {
            #pragma unroll
            for (int n = 0; n < TN; n++) {
                float nn = tanhf(gi[n] + rv[n] * gh[n]);
                outv[n] = (1.0f - zv[n]) * nn + zv[n] * xsn[n][t];
            }
        }
    }
    #pragma unroll
    for (int n = 0; n < TN; n++)
        out[(size_t)(n0 + n) * ND + t] = outv[n];
}

extern "C" void kernel_launch(void* const* d_in, const int* in_sizes, int n_in,
                              void* d_out, int out_size) {
    const float* nf     = (const float*)d_in[0];
    const int*   ei     = (const int*)d_in[1];
    const float* ef     = (const float*)d_in[2];
    const float* W1     = (const float*)d_in[3];
    const float* b1     = (const float*)d_in[4];
    const float* ln_g   = (const float*)d_in[5];
    const float* ln_b   = (const float*)d_in[6];
    const float* W2     = (const float*)d_in[7];
    const float* b2     = (const float*)d_in[8];
    const float* gate_w = (const float*)d_in[9];
    const float* gate_b = (const float*)d_in[10];
    const float* W_ih   = (const float*)d_in[11];
    const float* b_ih   = (const float*)d_in[12];
    const float* W_hh   = (const float*)d_in[13];
    const float* b_hh   = (const float*)d_in[14];
    float* out = (float*)d_out;

    zero_agg_kernel<<<592, 256>>>();
    edge_kernel<<<N_EDGES / TE, 128>>>(nf, ei, ef, W1, b1, ln_g, ln_b,
                                       W2, b2, gate_w, gate_b);
    gru_kernel<<<N_NODES / TN, 128>>>(nf, W_ih, b_ih, W_hh, b_hh, out);
}

// round 3
// speedup vs baseline: 1.1900x; 1.1900x over previous
#include <cuda_runtime.h>

#define N_NODES 40000
#define N_EDGES 640000
#define ND 128
#define ED 64
#define IN_DIM 320   // 2*ND + ED
#define TE 8         // edges per block (4 f32x2 pairs)
#define TN 16        // nodes per block (8 f32x2 pairs) in GRU

typedef unsigned long long u64;

__device__ __forceinline__ u64 pack2(float lo, float hi) {
    u64 r;
    asm("mov.b64 %0, {%1, %2};" : "=l"(r) : "f"(lo), "f"(hi));
    return r;
}
__device__ __forceinline__ void unpack2(u64 v, float& lo, float& hi) {
    asm("mov.b64 {%0, %1}, %2;" : "=f"(lo), "=f"(hi) : "l"(v));
}
// d = a*b + d  (two packed fp32 lanes)
__device__ __forceinline__ void ffma2(u64& d, u64 a, u64 b) {
    asm("fma.rn.f32x2 %0, %1, %2, %0;" : "+l"(d) : "l"(a), "l"(b));
}
__device__ __forceinline__ float sigmoidf_(float x) {
    return 1.0f / (1.0f + __expf(-x));
}

// Scratch accumulator for scatter-add (device global: no allocation).
__device__ float g_agg[(size_t)N_NODES * ND];

__global__ void zero_agg_kernel() {
    size_t total = (size_t)N_NODES * ND / 4;
    float4 z = make_float4(0.f, 0.f, 0.f, 0.f);
    for (size_t i = (size_t)blockIdx.x * blockDim.x + threadIdx.x; i < total;
         i += (size_t)gridDim.x * blockDim.x)
        ((float4*)g_agg)[i] = z;
}

__global__ __launch_bounds__(128) void edge_kernel(
    const float* __restrict__ nf, const int* __restrict__ ei,
    const float* __restrict__ ef, const float* __restrict__ W1,
    const float* __restrict__ b1, const float* __restrict__ ln_g,
    const float* __restrict__ ln_b, const float* __restrict__ W2,
    const float* __restrict__ b2, const float* __restrict__ gate_w,
    const float* __restrict__ gate_b)
{
    // Pair-interleaved activations: element [p][k] = (x[2p][k], x[2p+1][k])
    __shared__ __align__(16) u64 xsp[TE / 2][IN_DIM];
    __shared__ __align__(16) u64 hbp[TE / 2][ND];
    __shared__ float redS[TE][4], redQ[TE][4];
    __shared__ float gatev[TE];
    __shared__ int   dsts[TE];

    const int t = threadIdx.x;       // feature index 0..127
    const int warp = t >> 5, lane = t & 31;
    const int e0 = blockIdx.x * TE;

    // ---- Gather: warp w owns pair p=w (edges 2w, 2w+1) ----
    {
        float* bx = (float*)xsp[warp];
        #pragma unroll
        for (int h = 0; h < 2; h++) {
            int el = 2 * warp + h;
            int e  = e0 + el;
            int s  = ei[e];
            int d  = ei[N_EDGES + e];
            if (lane == 0) dsts[el] = d;
            const float* sr = nf + (size_t)s * ND;
            const float* dr = nf + (size_t)d * ND;
            #pragma unroll
            for (int c = 0; c < 4; c++) {
                int k = lane + 32 * c;
                bx[2 * k + h]        = sr[k];
                bx[2 * (ND + k) + h] = dr[k];
            }
            const float* er = ef + (size_t)e * ED;
            #pragma unroll
            for (int c = 0; c < 2; c++) {
                int k = lane + 32 * c;
                bx[2 * (2 * ND + k) + h] = er[k];
            }
        }
    }
    __syncthreads();

    // ---- Edge gate (8 threads, one per edge) from raw edge features ----
    if (t < TE) {
        const float* bx = (const float*)xsp[t >> 1];
        int h = t & 1;
        float g = gate_b[0];
        #pragma unroll 8
        for (int k = 0; k < ED; k++) g += bx[2 * (2 * ND + k) + h] * gate_w[k];
        gatev[t] = sigmoidf_(g);
    }

    // ---- Layer 1: packed over edge pairs ----
    u64 acc[TE / 2];
    {
        float b = b1[t];
        u64 bp = pack2(b, b);
        #pragma unroll
        for (int p = 0; p < TE / 2; p++) acc[p] = bp;
    }
    for (int k = 0; k < IN_DIM; k += 4) {
        float a0 = W1[(k + 0) * ND + t];
        float a1 = W1[(k + 1) * ND + t];
        float a2 = W1[(k + 2) * ND + t];
        float a3 = W1[(k + 3) * ND + t];
        u64 w0 = pack2(a0, a0), w1 = pack2(a1, a1);
        u64 w2 = pack2(a2, a2), w3 = pack2(a3, a3);
        #pragma unroll
        for (int p = 0; p < TE / 2; p++) {
            ulonglong2 xA = *(const ulonglong2*)&xsp[p][k];
            ulonglong2 xB = *(const ulonglong2*)&xsp[p][k + 2];
            ffma2(acc[p], w0, xA.x);
            ffma2(acc[p], w1, xA.y);
            ffma2(acc[p], w2, xB.x);
            ffma2(acc[p], w3, xB.y);
        }
    }

    // ---- LayerNorm: unpack, reduce across 128 threads ----
    float a[TE];
    #pragma unroll
    for (int p = 0; p < TE / 2; p++) unpack2(acc[p], a[2 * p], a[2 * p + 1]);
    {
        float s_[TE], q_[TE];
        #pragma unroll
        for (int e = 0; e < TE; e++) { s_[e] = a[e]; q_[e] = a[e] * a[e]; }
        #pragma unroll
        for (int off = 16; off > 0; off >>= 1) {
            #pragma unroll
            for (int e = 0; e < TE; e++) {
                s_[e] += __shfl_xor_sync(0xffffffff, s_[e], off);
                q_[e] += __shfl_xor_sync(0xffffffff, q_[e], off);
            }
        }
        if (lane == 0) {
            #pragma unroll
            for (int e = 0; e < TE; e++) { redS[e][warp] = s_[e]; redQ[e][warp] = q_[e]; }
        }
    }
    __syncthreads();
    {
        float g_ = ln_g[t], bb = ln_b[t];
        float* hf = (float*)hbp;
        #pragma unroll
        for (int e = 0; e < TE; e++) {
            float s  = redS[e][0] + redS[e][1] + redS[e][2] + redS[e][3];
            float q  = redQ[e][0] + redQ[e][1] + redQ[e][2] + redQ[e][3];
            float mu = s * (1.0f / ND);
            float var = q * (1.0f / ND) - mu * mu;
            float inv = rsqrtf(var + 1e-5f);
            float h = (a[e] - mu) * inv * g_ + bb;
            hf[2 * ((e >> 1) * ND + t) + (e & 1)] = fmaxf(h, 0.0f);
        }
    }
    __syncthreads();

    // ---- Layer 2: packed over edge pairs ----
    u64 acc2[TE / 2];
    {
        float b = b2[t];
        u64 bp = pack2(b, b);
        #pragma unroll
        for (int p = 0; p < TE / 2; p++) acc2[p] = bp;
    }
    for (int k = 0; k < ND; k += 4) {
        float a0 = W2[(k + 0) * ND + t];
        float a1 = W2[(k + 1) * ND + t];
        float a2 = W2[(k + 2) * ND + t];
        float a3 = W2[(k + 3) * ND + t];
        u64 w0 = pack2(a0, a0), w1 = pack2(a1, a1);
        u64 w2 = pack2(a2, a2), w3 = pack2(a3, a3);
        #pragma unroll
        for (int p = 0; p < TE / 2; p++) {
            ulonglong2 hA = *(const ulonglong2*)&hbp[p][k];
            ulonglong2 hB = *(const ulonglong2*)&hbp[p][k + 2];
            ffma2(acc2[p], w0, hA.x);
            ffma2(acc2[p], w1, hA.y);
            ffma2(acc2[p], w2, hB.x);
            ffma2(acc2[p], w3, hB.y);
        }
    }

    // ---- Gate + scatter-add ----
    #pragma unroll
    for (int p = 0; p < TE / 2; p++) {
        float m0, m1;
        unpack2(acc2[p], m0, m1);
        atomicAdd(&g_agg[(size_t)dsts[2 * p] * ND + t],     m0 * gatev[2 * p]);
        atomicAdd(&g_agg[(size_t)dsts[2 * p + 1] * ND + t], m1 * gatev[2 * p + 1]);
    }
}

__global__ __launch_bounds__(128) void gru_kernel(
    const float* __restrict__ nf, const float* __restrict__ W_ih,
    const float* __restrict__ b_ih, const float* __restrict__ W_hh,
    const float* __restrict__ b_hh, float* __restrict__ out)
{
    // Pair-interleaved over node pairs: [p][k] = (v[2p][k], v[2p+1][k])
    __shared__ __align__(16) u64 ap[TN / 2][ND];
    __shared__ __align__(16) u64 xp[TN / 2][ND];

    const int t = threadIdx.x;
    const int n0 = blockIdx.x * TN;

    {
        float* af = (float*)ap;
        float* xf = (float*)xp;
        #pragma unroll
        for (int i = 0; i < TN; i++) {
            int p = i >> 1, h = i & 1;
            af[2 * (p * ND + t) + h] = g_agg[(size_t)(n0 + i) * ND + t];
            xf[2 * (p * ND + t) + h] = nf[(size_t)(n0 + i) * ND + t];
        }
    }
    __syncthreads();

    float rv[TN], zv[TN], outv[TN];

    for (int g = 0; g < 3; g++) {   // torch gate order: r, z, n
        u64 gip[TN / 2], ghp[TN / 2];
        {
            float bi = b_ih[g * ND + t], bh = b_hh[g * ND + t];
            u64 bip = pack2(bi, bi), bhp = pack2(bh, bh);
            #pragma unroll
            for (int p = 0; p < TN / 2; p++) { gip[p] = bip; ghp[p] = bhp; }
        }
        const float4* wi = (const float4*)(W_ih + (size_t)(g * ND + t) * ND);
        const float4* wh = (const float4*)(W_hh + (size_t)(g * ND + t) * ND);
        for (int k4 = 0; k4 < ND / 4; k4++) {
            float4 wiv = wi[k4], whv = wh[k4];
            u64 i0 = pack2(wiv.x, wiv.x), i1 = pack2(wiv.y, wiv.y);
            u64 i2 = pack2(wiv.z, wiv.z), i3 = pack2(wiv.w, wiv.w);
            u64 h0 = pack2(whv.x, whv.x), h1 = pack2(whv.y, whv.y);
            u64 h2 = pack2(whv.z, whv.z), h3 = pack2(whv.w, whv.w);
            #pragma unroll
            for (int p = 0; p < TN / 2; p++) {
                ulonglong2 aA = *(const ulonglong2*)&ap[p][k4 * 4];
                ulonglong2 aB = *(const ulonglong2*)&ap[p][k4 * 4 + 2];
                ffma2(gip[p], i0, aA.x);
                ffma2(gip[p], i1, aA.y);
                ffma2(gip[p], i2, aB.x);
                ffma2(gip[p], i3, aB.y);
                ulonglong2 xA = *(const ulonglong2*)&xp[p][k4 * 4];
                ulonglong2 xB = *(const ulonglong2*)&xp[p][k4 * 4 + 2];
                ffma2(ghp[p], h0, xA.x);
                ffma2(ghp[p], h1, xA.y);
                ffma2(ghp[p], h2, xB.x);
                ffma2(ghp[p], h3, xB.y);
            }
        }
        #pragma unroll
        for (int p = 0; p < TN / 2; p++) {
            float gi0, gi1, gh0, gh1;
            unpack2(gip[p], gi0, gi1);
            unpack2(ghp[p], gh0, gh1);
            if (g == 0) {
                rv[2 * p]     = sigmoidf_(gi0 + gh0);
                rv[2 * p + 1] = sigmoidf_(gi1 + gh1);
            } else if (g == 1) {
                zv[2 * p]     = sigmoidf_(gi0 + gh0);
                zv[2 * p + 1] = sigmoidf_(gi1 + gh1);
            } else {
                float x0, x1;
                unpack2(xp[p][t], x0, x1);
                float nn0 = tanhf(gi0 + rv[2 * p] * gh0);
                float nn1 = tanhf(gi1 + rv[2 * p + 1] * gh1);
                outv[2 * p]     = (1.0f - zv[2 * p]) * nn0 + zv[2 * p] * x0;
                outv[2 * p + 1] = (1.0f - zv[2 * p + 1]) * nn1 + zv[2 * p + 1] * x1;
            }
        }
    }
    #pragma unroll
    for (int i = 0; i < TN; i++)
        out[(size_t)(n0 + i) * ND + t] = outv[i];
}

extern "C" void kernel_launch(void* const* d_in, const int* in_sizes, int n_in,
                              void* d_out, int out_size) {
    const float* nf     = (const float*)d_in[0];
    const int*   ei     = (const int*)d_in[1];
    const float* ef     = (const float*)d_in[2];
    const float* W1     = (const float*)d_in[3];
    const float* b1     = (const float*)d_in[4];
    const float* ln_g   = (const float*)d_in[5];
    const float* ln_b   = (const float*)d_in[6];
    const float* W2     = (const float*)d_in[7];
    const float* b2     = (const float*)d_in[8];
    const float* gate_w = (const float*)d_in[9];
    const float* gate_b = (const float*)d_in[10];
    const float* W_ih   = (const float*)d_in[11];
    const float* b_ih   = (const float*)d_in[12];
    const float* W_hh   = (const float*)d_in[13];
    const float* b_hh   = (const float*)d_in[14];
    float* out = (float*)d_out;

    zero_agg_kernel<<<592, 256>>>();
    edge_kernel<<<N_EDGES / TE, 128>>>(nf, ei, ef, W1, b1, ln_g, ln_b,
                                       W2, b2, gate_w, gate_b);
    gru_kernel<<<N_NODES / TN, 128>>>(nf, W_ih, b_ih, W_hh, b_hh, out);
}

// round 4
// speedup vs baseline: 1.1945x; 1.0038x over previous
#include <cuda_runtime.h>

#define N_NODES 40000
#define N_EDGES 640000
#define ND 128
#define ED 64
#define IN_DIM 320   // 2*ND + ED
#define TE 32        // edges per block (4 per warp)
#define THREADS 256
#define TN 16        // nodes per block (GRU)

typedef unsigned long long u64;

__device__ __forceinline__ u64 pack2(float lo, float hi) {
    u64 r;
    asm("mov.b64 %0, {%1, %2};" : "=l"(r) : "f"(lo), "f"(hi));
    return r;
}
__device__ __forceinline__ void unpack2(u64 v, float& lo, float& hi) {
    asm("mov.b64 {%0, %1}, %2;" : "=f"(lo), "=f"(hi) : "l"(v));
}
// d = a*b + d  (two packed fp32 lanes)
__device__ __forceinline__ void ffma2(u64& d, u64 a, u64 b) {
    asm("fma.rn.f32x2 %0, %1, %2, %0;" : "+l"(d) : "l"(a), "l"(b));
}
__device__ __forceinline__ float sigmoidf_(float x) {
    return 1.0f / (1.0f + __expf(-x));
}

// Device-global scratch (no allocation).
__device__ float g_agg[(size_t)N_NODES * ND];
__device__ u64 g_w1p[(IN_DIM / 2) * ND];  // (W1[2kp][o], W1[2kp+1][o])
__device__ u64 g_w2p[(ND / 2) * ND];

__global__ void zero_agg_kernel() {
    size_t total = (size_t)N_NODES * ND / 4;
    float4 z = make_float4(0.f, 0.f, 0.f, 0.f);
    for (size_t i = (size_t)blockIdx.x * blockDim.x + threadIdx.x; i < total;
         i += (size_t)gridDim.x * blockDim.x)
        ((float4*)g_agg)[i] = z;
}

__global__ void pack_w_kernel(const float* __restrict__ W1,
                              const float* __restrict__ W2) {
    int i = blockIdx.x * blockDim.x + threadIdx.x;
    if (i < (IN_DIM / 2) * ND) {
        int kp = i / ND, o = i % ND;
        g_w1p[i] = pack2(W1[(2 * kp) * ND + o], W1[(2 * kp + 1) * ND + o]);
    }
    if (i < (ND / 2) * ND) {
        int kp = i / ND, o = i % ND;
        g_w2p[i] = pack2(W2[(2 * kp) * ND + o], W2[(2 * kp + 1) * ND + o]);
    }
}

__global__ __launch_bounds__(THREADS) void edge_kernel(
    const float* __restrict__ nf, const int* __restrict__ ei,
    const float* __restrict__ ef, const float* __restrict__ b1,
    const float* __restrict__ ln_g, const float* __restrict__ ln_b,
    const float* __restrict__ b2, const float* __restrict__ gate_w,
    const float* __restrict__ gate_b)
{
    __shared__ __align__(16) float xs[TE][IN_DIM];  // per-warp private rows

    const int t = threadIdx.x;
    const int w = t >> 5, lane = t & 31;
    const int e0 = blockIdx.x * TE + w * 4;  // this warp's first edge
    const int o0 = lane * 4;                 // this thread's first output

    // ---- edge indices: lanes 0..3 hold (src,dst) of edges e0..e0+3 ----
    int sReg = 0, dReg = 0;
    if (lane < 4) {
        sReg = ei[e0 + lane];
        dReg = ei[N_EDGES + e0 + lane];
    }

    // ---- gather (warp-private rows, fully coalesced float4) ----
    #pragma unroll
    for (int e = 0; e < 4; e++) {
        int s = __shfl_sync(0xffffffffu, sReg, e);
        int d = __shfl_sync(0xffffffffu, dReg, e);
        float* row = xs[w * 4 + e];
        ((float4*)row)[lane]        = ((const float4*)(nf + (size_t)s * ND))[lane];
        ((float4*)(row + ND))[lane] = ((const float4*)(nf + (size_t)d * ND))[lane];
        if (lane < 16)
            ((float4*)(row + 2 * ND))[lane] =
                ((const float4*)(ef + (size_t)(e0 + e) * ED))[lane];
    }
    __syncwarp();

    // ---- sigmoid edge gate (warp-cooperative per edge) ----
    float gv[4];
    {
        float gw0 = gate_w[lane], gw1 = gate_w[lane + 32], gb = gate_b[0];
        #pragma unroll
        for (int e = 0; e < 4; e++) {
            const float* row = xs[w * 4 + e] + 2 * ND;
            float p = row[lane] * gw0 + row[lane + 32] * gw1;
            #pragma unroll
            for (int off = 16; off; off >>= 1)
                p += __shfl_xor_sync(0xffffffffu, p, off);
            gv[e] = sigmoidf_(p + gb);
        }
    }

    // ---- layer 1: acc[e][j] u64, lanes = k-even / k-odd partial sums ----
    u64 acc[16];
    #pragma unroll
    for (int i = 0; i < 16; i++) acc[i] = 0ull;

    for (int kp2 = 0; kp2 < IN_DIM / 4; kp2++) {
        const u64* wp = g_w1p + (size_t)(2 * kp2) * ND;
        ulonglong2 wA = *(const ulonglong2*)(wp + o0);            // kp0: o0,o0+1
        ulonglong2 wB = *(const ulonglong2*)(wp + o0 + 2);        // kp0: o0+2,o0+3
        ulonglong2 wC = *(const ulonglong2*)(wp + ND + o0);       // kp1: o0,o0+1
        ulonglong2 wD = *(const ulonglong2*)(wp + ND + o0 + 2);   // kp1: o0+2,o0+3
        #pragma unroll
        for (int e = 0; e < 4; e++) {
            ulonglong2 x = *(const ulonglong2*)&xs[w * 4 + e][4 * kp2];
            u64* a = acc + 4 * e;
            ffma2(a[0], wA.x, x.x);
            ffma2(a[1], wA.y, x.x);
            ffma2(a[2], wB.x, x.x);
            ffma2(a[3], wB.y, x.x);
            ffma2(a[0], wC.x, x.y);
            ffma2(a[1], wC.y, x.y);
            ffma2(a[2], wD.x, x.y);
            ffma2(a[3], wD.y, x.y);
        }
    }

    // ---- bias + LayerNorm + ReLU; overlay hs onto xs row [0..127] ----
    {
        float4 b1f = ((const float4*)b1)[lane];
        float4 lgf = ((const float4*)ln_g)[lane];
        float4 lbf = ((const float4*)ln_b)[lane];
        float b1a[4] = {b1f.x, b1f.y, b1f.z, b1f.w};
        float lga[4] = {lgf.x, lgf.y, lgf.z, lgf.w};
        float lba[4] = {lbf.x, lbf.y, lbf.z, lbf.w};
        #pragma unroll
        for (int e = 0; e < 4; e++) {
            float v[4], s = 0.f, q = 0.f;
            #pragma unroll
            for (int j = 0; j < 4; j++) {
                float lo, hi;
                unpack2(acc[4 * e + j], lo, hi);
                v[j] = lo + hi + b1a[j];
                s += v[j];
                q += v[j] * v[j];
            }
            #pragma unroll
            for (int off = 16; off; off >>= 1) {
                s += __shfl_xor_sync(0xffffffffu, s, off);
                q += __shfl_xor_sync(0xffffffffu, q, off);
            }
            float mu  = s * (1.0f / ND);
            float var = q * (1.0f / ND) - mu * mu;
            float inv = rsqrtf(var + 1e-5f);
            float4 hv;
            hv.x = fmaxf((v[0] - mu) * inv * lga[0] + lba[0], 0.f);
            hv.y = fmaxf((v[1] - mu) * inv * lga[1] + lba[1], 0.f);
            hv.z = fmaxf((v[2] - mu) * inv * lga[2] + lba[2], 0.f);
            hv.w = fmaxf((v[3] - mu) * inv * lga[3] + lba[3], 0.f);
            ((float4*)xs[w * 4 + e])[lane] = hv;  // hs overlay (warp-private)
        }
    }
    __syncwarp();

    // ---- layer 2 over hs (first 128 floats of each row) ----
    #pragma unroll
    for (int i = 0; i < 16; i++) acc[i] = 0ull;

    for (int kp2 = 0; kp2 < ND / 4; kp2++) {
        const u64* wp = g_w2p + (size_t)(2 * kp2) * ND;
        ulonglong2 wA = *(const ulonglong2*)(wp + o0);
        ulonglong2 wB = *(const ulonglong2*)(wp + o0 + 2);
        ulonglong2 wC = *(const ulonglong2*)(wp + ND + o0);
        ulonglong2 wD = *(const ulonglong2*)(wp + ND + o0 + 2);
        #pragma unroll
        for (int e = 0; e < 4; e++) {
            ulonglong2 x = *(const ulonglong2*)&xs[w * 4 + e][4 * kp2];
            u64* a = acc + 4 * e;
            ffma2(a[0], wA.x, x.x);
            ffma2(a[1], wA.y, x.x);
            ffma2(a[2], wB.x, x.x);
            ffma2(a[3], wB.y, x.x);
            ffma2(a[0], wC.x, x.y);
            ffma2(a[1], wC.y, x.y);
            ffma2(a[2], wD.x, x.y);
            ffma2(a[3], wD.y, x.y);
        }
    }

    // ---- bias + gate + scatter-add ----
    {
        float4 b2f = ((const float4*)b2)[lane];
        float b2a[4] = {b2f.x, b2f.y, b2f.z, b2f.w};
        #pragma unroll
        for (int e = 0; e < 4; e++) {
            int d = __shfl_sync(0xffffffffu, dReg, e);
            float* dstp = g_agg + (size_t)d * ND + o0;
            #pragma unroll
            for (int j = 0; j < 4; j++) {
                float lo, hi;
                unpack2(acc[4 * e + j], lo, hi);
                atomicAdd(dstp + j, (lo + hi + b2a[j]) * gv[e]);
            }
        }
    }
}

__global__ __launch_bounds__(128) void gru_kernel(
    const float* __restrict__ nf, const float* __restrict__ W_ih,
    const float* __restrict__ b_ih, const float* __restrict__ W_hh,
    const float* __restrict__ b_hh, float* __restrict__ out)
{
    // Pair-interleaved over node pairs: [p][k] = (v[2p][k], v[2p+1][k])
    __shared__ __align__(16) u64 ap[TN / 2][ND];
    __shared__ __align__(16) u64 xp[TN / 2][ND];

    const int t = threadIdx.x;
    const int n0 = blockIdx.x * TN;

    {
        float* af = (float*)ap;
        float* xf = (float*)xp;
        #pragma unroll
        for (int i = 0; i < TN; i++) {
            int p = i >> 1, h = i & 1;
            af[2 * (p * ND + t) + h] = g_agg[(size_t)(n0 + i) * ND + t];
            xf[2 * (p * ND + t) + h] = nf[(size_t)(n0 + i) * ND + t];
        }
    }
    __syncthreads();

    float rv[TN], zv[TN], outv[TN];

    for (int g = 0; g < 3; g++) {   // torch gate order: r, z, n
        u64 gip[TN / 2], ghp[TN / 2];
        {
            float bi = b_ih[g * ND + t], bh = b_hh[g * ND + t];
            u64 bip = pack2(bi, bi), bhp = pack2(bh, bh);
            #pragma unroll
            for (int p = 0; p < TN / 2; p++) { gip[p] = bip; ghp[p] = bhp; }
        }
        const float4* wi = (const float4*)(W_ih + (size_t)(g * ND + t) * ND);
        const float4* wh = (const float4*)(W_hh + (size_t)(g * ND + t) * ND);
        for (int k4 = 0; k4 < ND / 4; k4++) {
            float4 wiv = wi[k4], whv = wh[k4];
            u64 i0 = pack2(wiv.x, wiv.x), i1 = pack2(wiv.y, wiv.y);
            u64 i2 = pack2(wiv.z, wiv.z), i3 = pack2(wiv.w, wiv.w);
            u64 h0 = pack2(whv.x, whv.x), h1 = pack2(whv.y, whv.y);
            u64 h2 = pack2(whv.z, whv.z), h3 = pack2(whv.w, whv.w);
            #pragma unroll
            for (int p = 0; p < TN / 2; p++) {
                ulonglong2 aA = *(const ulonglong2*)&ap[p][k4 * 4];
                ulonglong2 aB = *(const ulonglong2*)&ap[p][k4 * 4 + 2];
                ffma2(gip[p], i0, aA.x);
                ffma2(gip[p], i1, aA.y);
                ffma2(gip[p], i2, aB.x);
                ffma2(gip[p], i3, aB.y);
                ulonglong2 xA = *(const ulonglong2*)&xp[p][k4 * 4];
                ulonglong2 xB = *(const ulonglong2*)&xp[p][k4 * 4 + 2];
                ffma2(ghp[p], h0, xA.x);
                ffma2(ghp[p], h1, xA.y);
                ffma2(ghp[p], h2, xB.x);
                ffma2(ghp[p], h3, xB.y);
            }
        }
        #pragma unroll
        for (int p = 0; p < TN / 2; p++) {
            float gi0, gi1, gh0, gh1;
            unpack2(gip[p], gi0, gi1);
            unpack2(ghp[p], gh0, gh1);
            if (g == 0) {
                rv[2 * p]     = sigmoidf_(gi0 + gh0);
                rv[2 * p + 1] = sigmoidf_(gi1 + gh1);
            } else if (g == 1) {
                zv[2 * p]     = sigmoidf_(gi0 + gh0);
                zv[2 * p + 1] = sigmoidf_(gi1 + gh1);
            } else {
                float x0, x1;
                unpack2(xp[p][t], x0, x1);
                float nn0 = tanhf(gi0 + rv[2 * p] * gh0);
                float nn1 = tanhf(gi1 + rv[2 * p + 1] * gh1);
                outv[2 * p]     = (1.0f - zv[2 * p]) * nn0 + zv[2 * p] * x0;
                outv[2 * p + 1] = (1.0f - zv[2 * p + 1]) * nn1 + zv[2 * p + 1] * x1;
            }
        }
    }
    #pragma unroll
    for (int i = 0; i < TN; i++)
        out[(size_t)(n0 + i) * ND + t] = outv[i];
}

extern "C" void kernel_launch(void* const* d_in, const int* in_sizes, int n_in,
                              void* d_out, int out_size) {
    const float* nf     = (const float*)d_in[0];
    const int*   ei     = (const int*)d_in[1];
    const float* ef     = (const float*)d_in[2];
    const float* W1     = (const float*)d_in[3];
    const float* b1     = (const float*)d_in[4];
    const float* ln_g   = (const float*)d_in[5];
    const float* ln_b   = (const float*)d_in[6];
    const float* W2     = (const float*)d_in[7];
    const float* b2     = (const float*)d_in[8];
    const float* gate_w = (const float*)d_in[9];
    const float* gate_b = (const float*)d_in[10];
    const float* W_ih   = (const float*)d_in[11];
    const float* b_ih   = (const float*)d_in[12];
    const float* W_hh   = (const float*)d_in[13];
    const float* b_hh   = (const float*)d_in[14];
    float* out = (float*)d_out;

    zero_agg_kernel<<<592, 256>>>();
    pack_w_kernel<<<(IN_DIM / 2 * ND + 255) / 256, 256>>>(W1, W2);
    edge_kernel<<<N_EDGES / TE, THREADS>>>(nf, ei, ef, b1, ln_g, ln_b,
                                           b2, gate_w, gate_b);
    gru_kernel<<<N_NODES / TN, 128>>>(nf, W_ih, b_ih, W_hh, b_hh, out);
}

// round 5
// speedup vs baseline: 2.5495x; 2.1344x over previous
#include <cuda_runtime.h>

#define N_NODES 40000
#define N_EDGES 640000
#define ND 128
#define ED 64
#define IN_DIM 320   // 2*ND + ED
#define NT 4         // edge tiles per block
#define EPW 8        // edges per warp

typedef unsigned long long u64;

__device__ __forceinline__ u64 pack2(float lo, float hi) {
    u64 r;
    asm("mov.b64 %0, {%1, %2};" : "=l"(r) : "f"(lo), "f"(hi));
    return r;
}
__device__ __forceinline__ void unpack2(u64 v, float& lo, float& hi) {
    asm("mov.b64 {%0, %1}, %2;" : "=f"(lo), "=f"(hi) : "l"(v));
}
__device__ __forceinline__ void ffma2(u64& d, u64 a, u64 b) {
    asm("fma.rn.f32x2 %0, %1, %2, %0;" : "+l"(d) : "l"(a), "l"(b));
}
__device__ __forceinline__ float sigmoidf_(float x) {
    return 1.0f / (1.0f + __expf(-x));
}

// Device-global scratch (no allocation).
__device__ float g_agg[(size_t)N_NODES * ND];
__device__ float g_P[(size_t)N_NODES * ND];     // nf @ W1a + b1
__device__ float g_Q[(size_t)N_NODES * ND];     // nf @ W1b
__device__ u64 g_w1p[(IN_DIM / 2) * ND];        // (W1[2kp][o], W1[2kp+1][o])
__device__ u64 g_w2p[(ND / 2) * ND];
__device__ u64 g_gruT[(ND / 2) * 768];          // [kp][ih:384 | hh:384], pack over k

__global__ void zero_agg_kernel() {
    size_t total = (size_t)N_NODES * ND / 4;
    float4 z = make_float4(0.f, 0.f, 0.f, 0.f);
    for (size_t i = (size_t)blockIdx.x * blockDim.x + threadIdx.x; i < total;
         i += (size_t)gridDim.x * blockDim.x)
        ((float4*)g_agg)[i] = z;
}

__global__ void prep_kernel(const float* __restrict__ W1,
                            const float* __restrict__ W2,
                            const float* __restrict__ W_ih,
                            const float* __restrict__ W_hh) {
    int i = blockIdx.x * blockDim.x + threadIdx.x;
    if (i < (IN_DIM / 2) * ND) {
        int kp = i >> 7, o = i & 127;
        g_w1p[i] = pack2(W1[(2 * kp) * ND + o], W1[(2 * kp + 1) * ND + o]);
    }
    if (i < (ND / 2) * ND) {
        int kp = i >> 7, o = i & 127;
        g_w2p[i] = pack2(W2[(2 * kp) * ND + o], W2[(2 * kp + 1) * ND + o]);
    }
    if (i < (ND / 2) * 768) {
        int kp = i / 768, r = i % 768;
        const float* W = (r < 384) ? W_ih : W_hh;
        int o = (r < 384) ? r : r - 384;
        g_gruT[i] = pack2(W[o * ND + 2 * kp], W[o * ND + 2 * kp + 1]);
    }
}

// P = nf @ W1a + b1 ; Q = nf @ W1b  (per node)
__global__ __launch_bounds__(256) void pq_kernel(const float* __restrict__ nf,
                                                 const float* __restrict__ b1) {
    __shared__ __align__(16) float sX[32][ND];
    const int t = threadIdx.x, w = t >> 5, lane = t & 31, o0 = lane * 4;
    const int n0 = blockIdx.x * 32;

    #pragma unroll
    for (int i = 0; i < 4; i++) {
        int n = w * 4 + i;
        ((float4*)sX[n])[lane] = ((const float4*)(nf + (size_t)(n0 + n) * ND))[lane];
    }
    __syncwarp();

    u64 aP[16], aQ[16];
    {
        float4 b1v = *(const float4*)(b1 + o0);
        float bb[4] = {b1v.x, b1v.y, b1v.z, b1v.w};
        #pragma unroll
        for (int i = 0; i < 4; i++)
            #pragma unroll
            for (int j = 0; j < 4; j++) {
                aP[4 * i + j] = pack2(bb[j], 0.f);
                aQ[4 * i + j] = 0ull;
            }
    }

    #pragma unroll 2
    for (int kp2 = 0; kp2 < 32; kp2++) {
        const u64* wp = g_w1p + (size_t)(2 * kp2) * ND;
        const u64* wq = g_w1p + (size_t)(64 + 2 * kp2) * ND;
        ulonglong2 pA = *(const ulonglong2*)(wp + o0);
        ulonglong2 pB = *(const ulonglong2*)(wp + o0 + 2);
        ulonglong2 pC = *(const ulonglong2*)(wp + ND + o0);
        ulonglong2 pD = *(const ulonglong2*)(wp + ND + o0 + 2);
        ulonglong2 qA = *(const ulonglong2*)(wq + o0);
        ulonglong2 qB = *(const ulonglong2*)(wq + o0 + 2);
        ulonglong2 qC = *(const ulonglong2*)(wq + ND + o0);
        ulonglong2 qD = *(const ulonglong2*)(wq + ND + o0 + 2);
        #pragma unroll
        for (int i = 0; i < 4; i++) {
            int n = w * 4 + i;
            ulonglong2 x = *(const ulonglong2*)&sX[n][4 * kp2];
            u64* p = aP + 4 * i;
            u64* q = aQ + 4 * i;
            ffma2(p[0], pA.x, x.x); ffma2(p[1], pA.y, x.x);
            ffma2(p[2], pB.x, x.x); ffma2(p[3], pB.y, x.x);
            ffma2(p[0], pC.x, x.y); ffma2(p[1], pC.y, x.y);
            ffma2(p[2], pD.x, x.y); ffma2(p[3], pD.y, x.y);
            ffma2(q[0], qA.x, x.x); ffma2(q[1], qA.y, x.x);
            ffma2(q[2], qB.x, x.x); ffma2(q[3], qB.y, x.x);
            ffma2(q[0], qC.x, x.y); ffma2(q[1], qC.y, x.y);
            ffma2(q[2], qD.x, x.y); ffma2(q[3], qD.y, x.y);
        }
    }
    #pragma unroll
    for (int i = 0; i < 4; i++) {
        int n = n0 + w * 4 + i;
        float4 pv, qv;
        float lo, hi;
        unpack2(aP[4 * i + 0], lo, hi); pv.x = lo + hi;
        unpack2(aP[4 * i + 1], lo, hi); pv.y = lo + hi;
        unpack2(aP[4 * i + 2], lo, hi); pv.z = lo + hi;
        unpack2(aP[4 * i + 3], lo, hi); pv.w = lo + hi;
        unpack2(aQ[4 * i + 0], lo, hi); qv.x = lo + hi;
        unpack2(aQ[4 * i + 1], lo, hi); qv.y = lo + hi;
        unpack2(aQ[4 * i + 2], lo, hi); qv.z = lo + hi;
        unpack2(aQ[4 * i + 3], lo, hi); qv.w = lo + hi;
        *(float4*)(g_P + (size_t)n * ND + o0) = pv;
        *(float4*)(g_Q + (size_t)n * ND + o0) = qv;
    }
}

// Edge kernel: R = ef@W1c, h = LN(P[src]+Q[dst]+R), msg = (relu(h)@W2+b2)*gate
__global__ __launch_bounds__(256, 1) void edge_kernel(
    const int* __restrict__ ei, const float* __restrict__ ef,
    const float* __restrict__ ln_g, const float* __restrict__ ln_b,
    const float* __restrict__ b2, const float* __restrict__ gate_w,
    const float* __restrict__ gate_b)
{
    extern __shared__ __align__(16) unsigned char smem_raw[];
    u64* sW1c = (u64*)smem_raw;                 // 32 kp x 128  (32 KB)
    u64* sW2  = sW1c + 32 * ND;                 // 64 kp x 128  (64 KB)
    float* ef_s = (float*)(sW2 + 64 * ND);      // 8 warps x 8 edges x 64 (16 KB)
    float* hs   = ef_s + 8 * EPW * ED;          // 8 warps x 8 edges x 128 (32 KB)

    const int t = threadIdx.x, w = t >> 5, lane = t & 31, o0 = lane * 4;

    // cooperative weight load into smem
    {
        const ulonglong2* s1 = (const ulonglong2*)(g_w1p + 128 * ND);
        ulonglong2* d1 = (ulonglong2*)sW1c;
        #pragma unroll
        for (int i = 0; i < 8; i++) d1[t + 256 * i] = s1[t + 256 * i];
        const ulonglong2* s2 = (const ulonglong2*)g_w2p;
        ulonglong2* d2 = (ulonglong2*)sW2;
        #pragma unroll
        for (int i = 0; i < 16; i++) d2[t + 256 * i] = s2[t + 256 * i];
    }
    const float gw0 = gate_w[lane], gw1 = gate_w[lane + 32], gb = gate_b[0];
    const float4 b2v = ((const float4*)b2)[lane];
    const float4 lgv = ((const float4*)ln_g)[lane];
    const float4 lbv = ((const float4*)ln_b)[lane];
    __syncthreads();

    float* efw = ef_s + w * EPW * ED;
    float* hsw = hs + w * EPW * ND;

    for (int it = 0; it < NT; it++) {
        const int e_base = (blockIdx.x * NT + it) * (8 * EPW) + w * EPW;
        int sReg = 0, dReg = 0;
        if (lane < EPW) {
            sReg = ei[e_base + lane];
            dReg = ei[N_EDGES + e_base + lane];
        }
        // load 8 edge-feature rows (64 f each): lanes cover 2 edges/pass
        #pragma unroll
        for (int pass = 0; pass < 4; pass++) {
            int e = pass * 2 + (lane >> 4);
            int idx = lane & 15;
            ((float4*)(efw + e * ED))[idx] =
                ((const float4*)(ef + (size_t)(e_base + e) * ED))[idx];
        }
        __syncwarp();

        // ---- R GEMM (K=64) ----
        u64 acc[32];
        #pragma unroll
        for (int i = 0; i < 32; i++) acc[i] = 0ull;
        #pragma unroll 2
        for (int kp2 = 0; kp2 < 16; kp2++) {
            const u64* wp = sW1c + (2 * kp2) * ND;
            ulonglong2 wA = *(const ulonglong2*)(wp + o0);
            ulonglong2 wB = *(const ulonglong2*)(wp + o0 + 2);
            ulonglong2 wC = *(const ulonglong2*)(wp + ND + o0);
            ulonglong2 wD = *(const ulonglong2*)(wp + ND + o0 + 2);
            #pragma unroll
            for (int e = 0; e < EPW; e++) {
                ulonglong2 x = *(const ulonglong2*)(efw + e * ED + 4 * kp2);
                u64* a = acc + 4 * e;
                ffma2(a[0], wA.x, x.x); ffma2(a[1], wA.y, x.x);
                ffma2(a[2], wB.x, x.x); ffma2(a[3], wB.y, x.x);
                ffma2(a[0], wC.x, x.y); ffma2(a[1], wC.y, x.y);
                ffma2(a[2], wD.x, x.y); ffma2(a[3], wD.y, x.y);
            }
        }

        // ---- add P[src] + Q[dst], LayerNorm, ReLU -> hs ----
        #pragma unroll
        for (int e = 0; e < EPW; e++) {
            int s = __shfl_sync(0xffffffffu, sReg, e);
            int d = __shfl_sync(0xffffffffu, dReg, e);
            float4 Pv = *(const float4*)(g_P + (size_t)s * ND + o0);
            float4 Qv = *(const float4*)(g_Q + (size_t)d * ND + o0);
            float v[4];
            float lo, hi;
            unpack2(acc[4 * e + 0], lo, hi); v[0] = lo + hi + Pv.x + Qv.x;
            unpack2(acc[4 * e + 1], lo, hi); v[1] = lo + hi + Pv.y + Qv.y;
            unpack2(acc[4 * e + 2], lo, hi); v[2] = lo + hi + Pv.z + Qv.z;
            unpack2(acc[4 * e + 3], lo, hi); v[3] = lo + hi + Pv.w + Qv.w;
            float sm = v[0] + v[1] + v[2] + v[3];
            float sq = v[0] * v[0] + v[1] * v[1] + v[2] * v[2] + v[3] * v[3];
            #pragma unroll
            for (int off = 16; off; off >>= 1) {
                sm += __shfl_xor_sync(0xffffffffu, sm, off);
                sq += __shfl_xor_sync(0xffffffffu, sq, off);
            }
            float mu  = sm * (1.0f / ND);
            float var = sq * (1.0f / ND) - mu * mu;
            float inv = rsqrtf(var + 1e-5f);
            float4 hv;
            hv.x = fmaxf((v[0] - mu) * inv * lgv.x + lbv.x, 0.f);
            hv.y = fmaxf((v[1] - mu) * inv * lgv.y + lbv.y, 0.f);
            hv.z = fmaxf((v[2] - mu) * inv * lgv.z + lbv.z, 0.f);
            hv.w = fmaxf((v[3] - mu) * inv * lgv.w + lbv.w, 0.f);
            ((float4*)(hsw + e * ND))[lane] = hv;
        }
        __syncwarp();

        // ---- sigmoid gate per edge ----
        float gv[EPW];
        #pragma unroll
        for (int e = 0; e < EPW; e++) {
            float p = efw[e * ED + lane] * gw0 + efw[e * ED + lane + 32] * gw1;
            #pragma unroll
            for (int off = 16; off; off >>= 1)
                p += __shfl_xor_sync(0xffffffffu, p, off);
            gv[e] = sigmoidf_(p + gb);
        }

        // ---- layer 2 GEMM (K=128) ----
        #pragma unroll
        for (int i = 0; i < 32; i++) acc[i] = 0ull;
        #pragma unroll 2
        for (int kp2 = 0; kp2 < 32; kp2++) {
            const u64* wp = sW2 + (2 * kp2) * ND;
            ulonglong2 wA = *(const ulonglong2*)(wp + o0);
            ulonglong2 wB = *(const ulonglong2*)(wp + o0 + 2);
            ulonglong2 wC = *(const ulonglong2*)(wp + ND + o0);
            ulonglong2 wD = *(const ulonglong2*)(wp + ND + o0 + 2);
            #pragma unroll
            for (int e = 0; e < EPW; e++) {
                ulonglong2 x = *(const ulonglong2*)(hsw + e * ND + 4 * kp2);
                u64* a = acc + 4 * e;
                ffma2(a[0], wA.x, x.x); ffma2(a[1], wA.y, x.x);
                ffma2(a[2], wB.x, x.x); ffma2(a[3], wB.y, x.x);
                ffma2(a[0], wC.x, x.y); ffma2(a[1], wC.y, x.y);
                ffma2(a[2], wD.x, x.y); ffma2(a[3], wD.y, x.y);
            }
        }

        // ---- bias + gate + scatter-add ----
        #pragma unroll
        for (int e = 0; e < EPW; e++) {
            int d = __shfl_sync(0xffffffffu, dReg, e);
            float* dp = g_agg + (size_t)d * ND + o0;
            float lo, hi;
            unpack2(acc[4 * e + 0], lo, hi); atomicAdd(dp + 0, (lo + hi + b2v.x) * gv[e]);
            unpack2(acc[4 * e + 1], lo, hi); atomicAdd(dp + 1, (lo + hi + b2v.y) * gv[e]);
            unpack2(acc[4 * e + 2], lo, hi); atomicAdd(dp + 2, (lo + hi + b2v.z) * gv[e]);
            unpack2(acc[4 * e + 3], lo, hi); atomicAdd(dp + 3, (lo + hi + b2v.w) * gv[e]);
        }
        __syncwarp();
    }
}

__global__ __launch_bounds__(256) void gru_kernel(
    const float* __restrict__ nf, const float* __restrict__ b_ih,
    const float* __restrict__ b_hh, float* __restrict__ out)
{
    __shared__ __align__(16) float sA[32][ND];
    __shared__ __align__(16) float sX[32][ND];
    const int t = threadIdx.x, w = t >> 5, lane = t & 31, o0 = lane * 4;
    const int n0 = blockIdx.x * 32;

    #pragma unroll
    for (int i = 0; i < 4; i++) {
        int n = w * 4 + i;
        ((float4*)sA[n])[lane] = ((const float4*)(g_agg + (size_t)(n0 + n) * ND))[lane];
        ((float4*)sX[n])[lane] = ((const float4*)(nf + (size_t)(n0 + n) * ND))[lane];
    }
    __syncwarp();

    float rv[16], zv[16];

    #pragma unroll
    for (int g = 0; g < 3; g++) {
        u64 gi[16], gh[16];
        {
            float4 biv = *(const float4*)(b_ih + g * ND + o0);
            float4 bhv = *(const float4*)(b_hh + g * ND + o0);
            float bi[4] = {biv.x, biv.y, biv.z, biv.w};
            float bh[4] = {bhv.x, bhv.y, bhv.z, bhv.w};
            #pragma unroll
            for (int i = 0; i < 4; i++)
                #pragma unroll
                for (int j = 0; j < 4; j++) {
                    gi[4 * i + j] = pack2(bi[j], 0.f);
                    gh[4 * i + j] = pack2(bh[j], 0.f);
                }
        }
        #pragma unroll 2
        for (int kp2 = 0; kp2 < 32; kp2++) {
            const u64* base0 = g_gruT + (size_t)(2 * kp2) * 768;
            const u64* base1 = base0 + 768;
            ulonglong2 iA = *(const ulonglong2*)(base0 + g * ND + o0);
            ulonglong2 iB = *(const ulonglong2*)(base0 + g * ND + o0 + 2);
            ulonglong2 iC = *(const ulonglong2*)(base1 + g * ND + o0);
            ulonglong2 iD = *(const ulonglong2*)(base1 + g * ND + o0 + 2);
            ulonglong2 hA = *(const ulonglong2*)(base0 + 384 + g * ND + o0);
            ulonglong2 hB = *(const ulonglong2*)(base0 + 384 + g * ND + o0 + 2);
            ulonglong2 hC = *(const ulonglong2*)(base1 + 384 + g * ND + o0);
            ulonglong2 hD = *(const ulonglong2*)(base1 + 384 + g * ND + o0 + 2);
            #pragma unroll
            for (int i = 0; i < 4; i++) {
                int n = w * 4 + i;
                ulonglong2 xa = *(const ulonglong2*)&sA[n][4 * kp2];
                ulonglong2 xx = *(const ulonglong2*)&sX[n][4 * kp2];
                u64* pi = gi + 4 * i;
                u64* ph = gh + 4 * i;
                ffma2(pi[0], iA.x, xa.x); ffma2(pi[1], iA.y, xa.x);
                ffma2(pi[2], iB.x, xa.x); ffma2(pi[3], iB.y, xa.x);
                ffma2(pi[0], iC.x, xa.y); ffma2(pi[1], iC.y, xa.y);
                ffma2(pi[2], iD.x, xa.y); ffma2(pi[3], iD.y, xa.y);
                ffma2(ph[0], hA.x, xx.x); ffma2(ph[1], hA.y, xx.x);
                ffma2(ph[2], hB.x, xx.x); ffma2(ph[3], hB.y, xx.x);
                ffma2(ph[0], hC.x, xx.y); ffma2(ph[1], hC.y, xx.y);
                ffma2(ph[2], hD.x, xx.y); ffma2(ph[3], hD.y, xx.y);
            }
        }
        #pragma unroll
        for (int i = 0; i < 4; i++) {
            int n = w * 4 + i;
            #pragma unroll
            for (int j = 0; j < 4; j++) {
                float il, ih, hl, hh;
                unpack2(gi[4 * i + j], il, ih);
                unpack2(gh[4 * i + j], hl, hh);
                float giv = il + ih, ghv = hl + hh;
                if (g == 0) {
                    rv[4 * i + j] = sigmoidf_(giv + ghv);
                } else if (g == 1) {
                    zv[4 * i + j] = sigmoidf_(giv + ghv);
                } else {
                    float nn = tanhf(giv + rv[4 * i + j] * ghv);
                    float x = sX[n][o0 + j];
                    float z = zv[4 * i + j];
                    // reuse rv as output storage
                    rv[4 * i + j] = (1.0f - z) * nn + z * x;
                }
            }
        }
    }
    #pragma unroll
    for (int i = 0; i < 4; i++) {
        int n = n0 + w * 4 + i;
        float4 ov = make_float4(rv[4 * i], rv[4 * i + 1], rv[4 * i + 2], rv[4 * i + 3]);
        *(float4*)(out + (size_t)n * ND + o0) = ov;
    }
}

#define EDGE_SMEM (32 * 128 * 8 + 64 * 128 * 8 + 8 * EPW * ED * 4 + 8 * EPW * ND * 4)

extern "C" void kernel_launch(void* const* d_in, const int* in_sizes, int n_in,
                              void* d_out, int out_size) {
    const float* nf     = (const float*)d_in[0];
    const int*   ei     = (const int*)d_in[1];
    const float* ef     = (const float*)d_in[2];
    const float* W1     = (const float*)d_in[3];
    const float* b1     = (const float*)d_in[4];
    const float* ln_g   = (const float*)d_in[5];
    const float* ln_b   = (const float*)d_in[6];
    const float* W2     = (const float*)d_in[7];
    const float* b2     = (const float*)d_in[8];
    const float* gate_w = (const float*)d_in[9];
    const float* gate_b = (const float*)d_in[10];
    const float* W_ih   = (const float*)d_in[11];
    const float* b_ih   = (const float*)d_in[12];
    const float* W_hh   = (const float*)d_in[13];
    const float* b_hh   = (const float*)d_in[14];
    float* out = (float*)d_out;

    cudaFuncSetAttribute(edge_kernel, cudaFuncAttributeMaxDynamicSharedMemorySize,
                         EDGE_SMEM);

    zero_agg_kernel<<<592, 256>>>();
    prep_kernel<<<192, 256>>>(W1, W2, W_ih, W_hh);
    pq_kernel<<<N_NODES / 32, 256>>>(nf, b1);
    edge_kernel<<<N_EDGES / (8 * EPW * NT), 256, EDGE_SMEM>>>(
        ei, ef, ln_g, ln_b, b2, gate_w, gate_b);
    gru_kernel<<<N_NODES / 32, 256>>>(nf, b_ih, b_hh, out);
}

// round 6
// speedup vs baseline: 2.7835x; 1.0918x over previous
#include <cuda_runtime.h>

#define N_NODES 40000
#define N_EDGES 640000
#define ND 128
#define ED 64
#define IN_DIM 320   // 2*ND + ED
#define NT 4         // edge tiles per block
#define EPW 8        // edges per warp

typedef unsigned long long u64;

__device__ __forceinline__ u64 pack2(float lo, float hi) {
    u64 r;
    asm("mov.b64 %0, {%1, %2};" : "=l"(r) : "f"(lo), "f"(hi));
    return r;
}
__device__ __forceinline__ void unpack2(u64 v, float& lo, float& hi) {
    asm("mov.b64 {%0, %1}, %2;" : "=f"(lo), "=f"(hi) : "l"(v));
}
__device__ __forceinline__ void ffma2(u64& d, u64 a, u64 b) {
    asm("fma.rn.f32x2 %0, %1, %2, %0;" : "+l"(d) : "l"(a), "l"(b));
}
__device__ __forceinline__ void red_add_v4(float* p, float a, float b, float c,
                                           float d) {
    asm volatile("red.global.add.v4.f32 [%0], {%1, %2, %3, %4};"
                 :: "l"(p), "f"(a), "f"(b), "f"(c), "f"(d) : "memory");
}
__device__ __forceinline__ float sigmoidf_(float x) {
    return 1.0f / (1.0f + __expf(-x));
}

// Device-global scratch (no allocation).
__device__ float g_agg[(size_t)N_NODES * ND];
__device__ float g_P[(size_t)N_NODES * ND];     // nf @ W1a + b1
__device__ float g_Q[(size_t)N_NODES * ND];     // nf @ W1b
__device__ u64 g_w1p[(IN_DIM / 2) * ND];        // (W1[2kp][o], W1[2kp+1][o])
__device__ u64 g_w2p[(ND / 2) * ND];
__device__ u64 g_gruT[(ND / 2) * 768];          // [kp][ih:384 | hh:384], pack over k

__global__ void zero_agg_kernel() {
    size_t total = (size_t)N_NODES * ND / 4;
    float4 z = make_float4(0.f, 0.f, 0.f, 0.f);
    for (size_t i = (size_t)blockIdx.x * blockDim.x + threadIdx.x; i < total;
         i += (size_t)gridDim.x * blockDim.x)
        ((float4*)g_agg)[i] = z;
}

__global__ void prep_kernel(const float* __restrict__ W1,
                            const float* __restrict__ W2,
                            const float* __restrict__ W_ih,
                            const float* __restrict__ W_hh) {
    int i = blockIdx.x * blockDim.x + threadIdx.x;
    if (i < (IN_DIM / 2) * ND) {
        int kp = i >> 7, o = i & 127;
        g_w1p[i] = pack2(W1[(2 * kp) * ND + o], W1[(2 * kp + 1) * ND + o]);
    }
    if (i < (ND / 2) * ND) {
        int kp = i >> 7, o = i & 127;
        g_w2p[i] = pack2(W2[(2 * kp) * ND + o], W2[(2 * kp + 1) * ND + o]);
    }
    if (i < (ND / 2) * 768) {
        int kp = i / 768, r = i % 768;
        const float* W = (r < 384) ? W_ih : W_hh;
        int o = (r < 384) ? r : r - 384;
        g_gruT[i] = pack2(W[o * ND + 2 * kp], W[o * ND + 2 * kp + 1]);
    }
}

// P = nf @ W1a + b1 ; Q = nf @ W1b  (per node), 64 nodes/block
__global__ __launch_bounds__(512) void pq_kernel(const float* __restrict__ nf,
                                                 const float* __restrict__ b1) {
    __shared__ __align__(16) float sX[64][ND];
    const int t = threadIdx.x, w = t >> 5, lane = t & 31, o0 = lane * 4;
    const int n0 = blockIdx.x * 64;

    #pragma unroll
    for (int i = 0; i < 4; i++) {
        int n = w * 4 + i;
        ((float4*)sX[n])[lane] = ((const float4*)(nf + (size_t)(n0 + n) * ND))[lane];
    }
    __syncwarp();

    u64 aP[16], aQ[16];
    {
        float4 b1v = *(const float4*)(b1 + o0);
        float bb[4] = {b1v.x, b1v.y, b1v.z, b1v.w};
        #pragma unroll
        for (int i = 0; i < 4; i++)
            #pragma unroll
            for (int j = 0; j < 4; j++) {
                aP[4 * i + j] = pack2(bb[j], 0.f);
                aQ[4 * i + j] = 0ull;
            }
    }

    #pragma unroll 2
    for (int kp2 = 0; kp2 < 32; kp2++) {
        const u64* wp = g_w1p + (size_t)(2 * kp2) * ND;
        const u64* wq = g_w1p + (size_t)(64 + 2 * kp2) * ND;
        ulonglong2 pA = *(const ulonglong2*)(wp + o0);
        ulonglong2 pB = *(const ulonglong2*)(wp + o0 + 2);
        ulonglong2 pC = *(const ulonglong2*)(wp + ND + o0);
        ulonglong2 pD = *(const ulonglong2*)(wp + ND + o0 + 2);
        ulonglong2 qA = *(const ulonglong2*)(wq + o0);
        ulonglong2 qB = *(const ulonglong2*)(wq + o0 + 2);
        ulonglong2 qC = *(const ulonglong2*)(wq + ND + o0);
        ulonglong2 qD = *(const ulonglong2*)(wq + ND + o0 + 2);
        #pragma unroll
        for (int i = 0; i < 4; i++) {
            int n = w * 4 + i;
            ulonglong2 x = *(const ulonglong2*)&sX[n][4 * kp2];
            u64* p = aP + 4 * i;
            u64* q = aQ + 4 * i;
            ffma2(p[0], pA.x, x.x); ffma2(p[1], pA.y, x.x);
            ffma2(p[2], pB.x, x.x); ffma2(p[3], pB.y, x.x);
            ffma2(p[0], pC.x, x.y); ffma2(p[1], pC.y, x.y);
            ffma2(p[2], pD.x, x.y); ffma2(p[3], pD.y, x.y);
            ffma2(q[0], qA.x, x.x); ffma2(q[1], qA.y, x.x);
            ffma2(q[2], qB.x, x.x); ffma2(q[3], qB.y, x.x);
            ffma2(q[0], qC.x, x.y); ffma2(q[1], qC.y, x.y);
            ffma2(q[2], qD.x, x.y); ffma2(q[3], qD.y, x.y);
        }
    }
    #pragma unroll
    for (int i = 0; i < 4; i++) {
        int n = n0 + w * 4 + i;
        float4 pv, qv;
        float lo, hi;
        unpack2(aP[4 * i + 0], lo, hi); pv.x = lo + hi;
        unpack2(aP[4 * i + 1], lo, hi); pv.y = lo + hi;
        unpack2(aP[4 * i + 2], lo, hi); pv.z = lo + hi;
        unpack2(aP[4 * i + 3], lo, hi); pv.w = lo + hi;
        unpack2(aQ[4 * i + 0], lo, hi); qv.x = lo + hi;
        unpack2(aQ[4 * i + 1], lo, hi); qv.y = lo + hi;
        unpack2(aQ[4 * i + 2], lo, hi); qv.z = lo + hi;
        unpack2(aQ[4 * i + 3], lo, hi); qv.w = lo + hi;
        *(float4*)(g_P + (size_t)n * ND + o0) = pv;
        *(float4*)(g_Q + (size_t)n * ND + o0) = qv;
    }
}

// Edge kernel: R = ef@W1c, h = LN(P[src]+Q[dst]+R), msg = (relu(h)@W2+b2)*gate
__global__ __launch_bounds__(256, 1) void edge_kernel(
    const int* __restrict__ ei, const float* __restrict__ ef,
    const float* __restrict__ ln_g, const float* __restrict__ ln_b,
    const float* __restrict__ b2, const float* __restrict__ gate_w,
    const float* __restrict__ gate_b)
{
    extern __shared__ __align__(16) unsigned char smem_raw[];
    u64* sW1c = (u64*)smem_raw;                 // 32 kp x 128  (32 KB)
    u64* sW2  = sW1c + 32 * ND;                 // 64 kp x 128  (64 KB)
    float* ef_s = (float*)(sW2 + 64 * ND);      // 8 warps x 8 edges x 64 (16 KB)
    float* hs   = ef_s + 8 * EPW * ED;          // 8 warps x 8 edges x 128 (32 KB)

    const int t = threadIdx.x, w = t >> 5, lane = t & 31, o0 = lane * 4;

    // cooperative weight load into smem
    {
        const ulonglong2* s1 = (const ulonglong2*)(g_w1p + 128 * ND);
        ulonglong2* d1 = (ulonglong2*)sW1c;
        #pragma unroll
        for (int i = 0; i < 8; i++) d1[t + 256 * i] = s1[t + 256 * i];
        const ulonglong2* s2 = (const ulonglong2*)g_w2p;
        ulonglong2* d2 = (ulonglong2*)sW2;
        #pragma unroll
        for (int i = 0; i < 16; i++) d2[t + 256 * i] = s2[t + 256 * i];
    }
    const float gw0 = gate_w[lane], gw1 = gate_w[lane + 32], gb = gate_b[0];
    const float4 b2v = ((const float4*)b2)[lane];
    const float4 lgv = ((const float4*)ln_g)[lane];
    const float4 lbv = ((const float4*)ln_b)[lane];
    __syncthreads();

    float* efw = ef_s + w * EPW * ED;
    float* hsw = hs + w * EPW * ND;

    for (int it = 0; it < NT; it++) {
        const int e_base = (blockIdx.x * NT + it) * (8 * EPW) + w * EPW;
        int sReg = 0, dReg = 0;
        if (lane < EPW) {
            sReg = ei[e_base + lane];
            dReg = ei[N_EDGES + e_base + lane];
        }
        // load 8 edge-feature rows (64 f each): lanes cover 2 edges/pass
        #pragma unroll
        for (int pass = 0; pass < 4; pass++) {
            int e = pass * 2 + (lane >> 4);
            int idx = lane & 15;
            ((float4*)(efw + e * ED))[idx] =
                ((const float4*)(ef + (size_t)(e_base + e) * ED))[idx];
        }
        __syncwarp();

        // ---- R GEMM (K=64) ----
        u64 acc[32];
        #pragma unroll
        for (int i = 0; i < 32; i++) acc[i] = 0ull;
        #pragma unroll 2
        for (int kp2 = 0; kp2 < 16; kp2++) {
            const u64* wp = sW1c + (2 * kp2) * ND;
            ulonglong2 wA = *(const ulonglong2*)(wp + o0);
            ulonglong2 wB = *(const ulonglong2*)(wp + o0 + 2);
            ulonglong2 wC = *(const ulonglong2*)(wp + ND + o0);
            ulonglong2 wD = *(const ulonglong2*)(wp + ND + o0 + 2);
            #pragma unroll
            for (int e = 0; e < EPW; e++) {
                ulonglong2 x = *(const ulonglong2*)(efw + e * ED + 4 * kp2);
                u64* a = acc + 4 * e;
                ffma2(a[0], wA.x, x.x); ffma2(a[1], wA.y, x.x);
                ffma2(a[2], wB.x, x.x); ffma2(a[3], wB.y, x.x);
                ffma2(a[0], wC.x, x.y); ffma2(a[1], wC.y, x.y);
                ffma2(a[2], wD.x, x.y); ffma2(a[3], wD.y, x.y);
            }
        }

        // ---- add P[src] + Q[dst], LayerNorm, ReLU -> hs ----
        #pragma unroll
        for (int e = 0; e < EPW; e++) {
            int s = __shfl_sync(0xffffffffu, sReg, e);
            int d = __shfl_sync(0xffffffffu, dReg, e);
            float4 Pv = *(const float4*)(g_P + (size_t)s * ND + o0);
            float4 Qv = *(const float4*)(g_Q + (size_t)d * ND + o0);
            float v[4];
            float lo, hi;
            unpack2(acc[4 * e + 0], lo, hi); v[0] = lo + hi + Pv.x + Qv.x;
            unpack2(acc[4 * e + 1], lo, hi); v[1] = lo + hi + Pv.y + Qv.y;
            unpack2(acc[4 * e + 2], lo, hi); v[2] = lo + hi + Pv.z + Qv.z;
            unpack2(acc[4 * e + 3], lo, hi); v[3] = lo + hi + Pv.w + Qv.w;
            float sm = v[0] + v[1] + v[2] + v[3];
            float sq = v[0] * v[0] + v[1] * v[1] + v[2] * v[2] + v[3] * v[3];
            #pragma unroll
            for (int off = 16; off; off >>= 1) {
                sm += __shfl_xor_sync(0xffffffffu, sm, off);
                sq += __shfl_xor_sync(0xffffffffu, sq, off);
            }
            float mu  = sm * (1.0f / ND);
            float var = sq * (1.0f / ND) - mu * mu;
            float inv = rsqrtf(var + 1e-5f);
            float4 hv;
            hv.x = fmaxf((v[0] - mu) * inv * lgv.x + lbv.x, 0.f);
            hv.y = fmaxf((v[1] - mu) * inv * lgv.y + lbv.y, 0.f);
            hv.z = fmaxf((v[2] - mu) * inv * lgv.z + lbv.z, 0.f);
            hv.w = fmaxf((v[3] - mu) * inv * lgv.w + lbv.w, 0.f);
            ((float4*)(hsw + e * ND))[lane] = hv;
        }
        __syncwarp();

        // ---- sigmoid gate per edge ----
        float gv[EPW];
        #pragma unroll
        for (int e = 0; e < EPW; e++) {
            float p = efw[e * ED + lane] * gw0 + efw[e * ED + lane + 32] * gw1;
            #pragma unroll
            for (int off = 16; off; off >>= 1)
                p += __shfl_xor_sync(0xffffffffu, p, off);
            gv[e] = sigmoidf_(p + gb);
        }

        // ---- layer 2 GEMM (K=128) ----
        #pragma unroll
        for (int i = 0; i < 32; i++) acc[i] = 0ull;
        #pragma unroll 2
        for (int kp2 = 0; kp2 < 32; kp2++) {
            const u64* wp = sW2 + (2 * kp2) * ND;
            ulonglong2 wA = *(const ulonglong2*)(wp + o0);
            ulonglong2 wB = *(const ulonglong2*)(wp + o0 + 2);
            ulonglong2 wC = *(const ulonglong2*)(wp + ND + o0);
            ulonglong2 wD = *(const ulonglong2*)(wp + ND + o0 + 2);
            #pragma unroll
            for (int e = 0; e < EPW; e++) {
                ulonglong2 x = *(const ulonglong2*)(hsw + e * ND + 4 * kp2);
                u64* a = acc + 4 * e;
                ffma2(a[0], wA.x, x.x); ffma2(a[1], wA.y, x.x);
                ffma2(a[2], wB.x, x.x); ffma2(a[3], wB.y, x.x);
                ffma2(a[0], wC.x, x.y); ffma2(a[1], wC.y, x.y);
                ffma2(a[2], wD.x, x.y); ffma2(a[3], wD.y, x.y);
            }
        }

        // ---- bias + gate + vectorized scatter-add ----
        #pragma unroll
        for (int e = 0; e < EPW; e++) {
            int d = __shfl_sync(0xffffffffu, dReg, e);
            float* dp = g_agg + (size_t)d * ND + o0;
            float lo, hi, m0, m1, m2, m3;
            unpack2(acc[4 * e + 0], lo, hi); m0 = (lo + hi + b2v.x) * gv[e];
            unpack2(acc[4 * e + 1], lo, hi); m1 = (lo + hi + b2v.y) * gv[e];
            unpack2(acc[4 * e + 2], lo, hi); m2 = (lo + hi + b2v.z) * gv[e];
            unpack2(acc[4 * e + 3], lo, hi); m3 = (lo + hi + b2v.w) * gv[e];
            red_add_v4(dp, m0, m1, m2, m3);
        }
        __syncwarp();
    }
}

__global__ __launch_bounds__(512) void gru_kernel(
    const float* __restrict__ nf, const float* __restrict__ b_ih,
    const float* __restrict__ b_hh, float* __restrict__ out)
{
    __shared__ __align__(16) float sA[64][ND];
    __shared__ __align__(16) float sX[64][ND];
    const int t = threadIdx.x, w = t >> 5, lane = t & 31, o0 = lane * 4;
    const int n0 = blockIdx.x * 64;

    #pragma unroll
    for (int i = 0; i < 4; i++) {
        int n = w * 4 + i;
        ((float4*)sA[n])[lane] = ((const float4*)(g_agg + (size_t)(n0 + n) * ND))[lane];
        ((float4*)sX[n])[lane] = ((const float4*)(nf + (size_t)(n0 + n) * ND))[lane];
    }
    __syncwarp();

    float rv[16], zv[16];

    #pragma unroll
    for (int g = 0; g < 3; g++) {
        u64 gi[16], gh[16];
        {
            float4 biv = *(const float4*)(b_ih + g * ND + o0);
            float4 bhv = *(const float4*)(b_hh + g * ND + o0);
            float bi[4] = {biv.x, biv.y, biv.z, biv.w};
            float bh[4] = {bhv.x, bhv.y, bhv.z, bhv.w};
            #pragma unroll
            for (int i = 0; i < 4; i++)
                #pragma unroll
                for (int j = 0; j < 4; j++) {
                    gi[4 * i + j] = pack2(bi[j], 0.f);
                    gh[4 * i + j] = pack2(bh[j], 0.f);
                }
        }
        #pragma unroll 2
        for (int kp2 = 0; kp2 < 32; kp2++) {
            const u64* base0 = g_gruT + (size_t)(2 * kp2) * 768;
            const u64* base1 = base0 + 768;
            ulonglong2 iA = *(const ulonglong2*)(base0 + g * ND + o0);
            ulonglong2 iB = *(const ulonglong2*)(base0 + g * ND + o0 + 2);
            ulonglong2 iC = *(const ulonglong2*)(base1 + g * ND + o0);
            ulonglong2 iD = *(const ulonglong2*)(base1 + g * ND + o0 + 2);
            ulonglong2 hA = *(const ulonglong2*)(base0 + 384 + g * ND + o0);
            ulonglong2 hB = *(const ulonglong2*)(base0 + 384 + g * ND + o0 + 2);
            ulonglong2 hC = *(const ulonglong2*)(base1 + 384 + g * ND + o0);
            ulonglong2 hD = *(const ulonglong2*)(base1 + 384 + g * ND + o0 + 2);
            #pragma unroll
            for (int i = 0; i < 4; i++) {
                int n = w * 4 + i;
                ulonglong2 xa = *(const ulonglong2*)&sA[n][4 * kp2];
                ulonglong2 xx = *(const ulonglong2*)&sX[n][4 * kp2];
                u64* pi = gi + 4 * i;
                u64* ph = gh + 4 * i;
                ffma2(pi[0], iA.x, xa.x); ffma2(pi[1], iA.y, xa.x);
                ffma2(pi[2], iB.x, xa.x); ffma2(pi[3], iB.y, xa.x);
                ffma2(pi[0], iC.x, xa.y); ffma2(pi[1], iC.y, xa.y);
                ffma2(pi[2], iD.x, xa.y); ffma2(pi[3], iD.y, xa.y);
                ffma2(ph[0], hA.x, xx.x); ffma2(ph[1], hA.y, xx.x);
                ffma2(ph[2], hB.x, xx.x); ffma2(ph[3], hB.y, xx.x);
                ffma2(ph[0], hC.x, xx.y); ffma2(ph[1], hC.y, xx.y);
                ffma2(ph[2], hD.x, xx.y); ffma2(ph[3], hD.y, xx.y);
            }
        }
        #pragma unroll
        for (int i = 0; i < 4; i++) {
            int n = w * 4 + i;
            #pragma unroll
            for (int j = 0; j < 4; j++) {
                float il, ih, hl, hh;
                unpack2(gi[4 * i + j], il, ih);
                unpack2(gh[4 * i + j], hl, hh);
                float giv = il + ih, ghv = hl + hh;
                if (g == 0) {
                    rv[4 * i + j] = sigmoidf_(giv + ghv);
                } else if (g == 1) {
                    zv[4 * i + j] = sigmoidf_(giv + ghv);
                } else {
                    float nn = tanhf(giv + rv[4 * i + j] * ghv);
                    float x = sX[n][o0 + j];
                    float z = zv[4 * i + j];
                    rv[4 * i + j] = (1.0f - z) * nn + z * x;
                }
            }
        }
    }
    #pragma unroll
    for (int i = 0; i < 4; i++) {
        int n = n0 + w * 4 + i;
        float4 ov = make_float4(rv[4 * i], rv[4 * i + 1], rv[4 * i + 2], rv[4 * i + 3]);
        *(float4*)(out + (size_t)n * ND + o0) = ov;
    }
}

#define EDGE_SMEM (32 * 128 * 8 + 64 * 128 * 8 + 8 * EPW * ED * 4 + 8 * EPW * ND * 4)

extern "C" void kernel_launch(void* const* d_in, const int* in_sizes, int n_in,
                              void* d_out, int out_size) {
    const float* nf     = (const float*)d_in[0];
    const int*   ei     = (const int*)d_in[1];
    const float* ef     = (const float*)d_in[2];
    const float* W1     = (const float*)d_in[3];
    const float* b1     = (const float*)d_in[4];
    const float* ln_g   = (const float*)d_in[5];
    const float* ln_b   = (const float*)d_in[6];
    const float* W2     = (const float*)d_in[7];
    const float* b2     = (const float*)d_in[8];
    const float* gate_w = (const float*)d_in[9];
    const float* gate_b = (const float*)d_in[10];
    const float* W_ih   = (const float*)d_in[11];
    const float* b_ih   = (const float*)d_in[12];
    const float* W_hh   = (const float*)d_in[13];
    const float* b_hh   = (const float*)d_in[14];
    float* out = (float*)d_out;

    cudaFuncSetAttribute(edge_kernel, cudaFuncAttributeMaxDynamicSharedMemorySize,
                         EDGE_SMEM);

    zero_agg_kernel<<<592, 256>>>();
    prep_kernel<<<192, 256>>>(W1, W2, W_ih, W_hh);
    pq_kernel<<<N_NODES / 64, 512>>>(nf, b1);
    edge_kernel<<<N_EDGES / (8 * EPW * NT), 256, EDGE_SMEM>>>(
        ei, ef, ln_g, ln_b, b2, gate_w, gate_b);
    gru_kernel<<<N_NODES / 64, 512>>>(nf, b_ih, b_hh, out);
}

// round 7
// speedup vs baseline: 3.1000x; 1.1137x over previous
#include <cuda_runtime.h>

#define N_NODES 40000
#define N_EDGES 640000
#define ND 128
#define ED 64
#define IN_DIM 320   // 2*ND + ED
#define NT 4         // edge tiles per block
#define EPW 8        // edges per warp

typedef unsigned long long u64;

__device__ __forceinline__ u64 pack2(float lo, float hi) {
    u64 r;
    asm("mov.b64 %0, {%1, %2};" : "=l"(r) : "f"(lo), "f"(hi));
    return r;
}
__device__ __forceinline__ void unpack2(u64 v, float& lo, float& hi) {
    asm("mov.b64 {%0, %1}, %2;" : "=f"(lo), "=f"(hi) : "l"(v));
}
__device__ __forceinline__ void ffma2(u64& d, u64 a, u64 b) {
    asm("fma.rn.f32x2 %0, %1, %2, %0;" : "+l"(d) : "l"(a), "l"(b));
}
__device__ __forceinline__ void red_add_v4(float* p, float a, float b, float c,
                                           float d) {
    asm volatile("red.global.add.v4.f32 [%0], {%1, %2, %3, %4};"
                 :: "l"(p), "f"(a), "f"(b), "f"(c), "f"(d) : "memory");
}
__device__ __forceinline__ float sigmoidf_(float x) {
    return 1.0f / (1.0f + __expf(-x));
}
// Output permutation: thread lane owns logical outputs {4l..4l+3}; physical
// slots are arranged so load#1 (lane*16B) = {4l,4l+1}, load#2 (+512B) = {4l+2,4l+3}.
__device__ __forceinline__ int physo(int o) {
    return ((o & 2) << 5) | ((o >> 2) << 1) | (o & 1);
}

// Device-global scratch (no allocation).
__device__ float g_agg[(size_t)N_NODES * ND];
__device__ float g_P[(size_t)N_NODES * ND];     // nf @ W1a + b1
__device__ float g_Q[(size_t)N_NODES * ND];     // nf @ W1b
__device__ u64 g_w1p[(IN_DIM / 2) * ND];        // [kp][phys(o)] = (W1[2kp][o], W1[2kp+1][o])
__device__ u64 g_w2p[(ND / 2) * ND];
__device__ u64 g_gruT[(ND / 2) * 768];          // [kp][ih:384 | hh:384], permuted per 128

__global__ void zero_agg_kernel() {
    size_t total = (size_t)N_NODES * ND / 4;
    float4 z = make_float4(0.f, 0.f, 0.f, 0.f);
    for (size_t i = (size_t)blockIdx.x * blockDim.x + threadIdx.x; i < total;
         i += (size_t)gridDim.x * blockDim.x)
        ((float4*)g_agg)[i] = z;
}

__global__ void prep_kernel(const float* __restrict__ W1,
                            const float* __restrict__ W2,
                            const float* __restrict__ W_ih,
                            const float* __restrict__ W_hh) {
    int i = blockIdx.x * blockDim.x + threadIdx.x;
    if (i < (IN_DIM / 2) * ND) {
        int kp = i >> 7, o = i & 127;
        g_w1p[(kp << 7) + physo(o)] =
            pack2(W1[(2 * kp) * ND + o], W1[(2 * kp + 1) * ND + o]);
    }
    if (i < (ND / 2) * ND) {
        int kp = i >> 7, o = i & 127;
        g_w2p[(kp << 7) + physo(o)] =
            pack2(W2[(2 * kp) * ND + o], W2[(2 * kp + 1) * ND + o]);
    }
    if (i < (ND / 2) * 768) {
        int kp = i / 768, r = i % 768;
        const float* W = (r < 384) ? W_ih : W_hh;
        int of = (r < 384) ? r : r - 384;       // gate*128 + o
        int g = of >> 7, o = of & 127;
        int slot = ((r < 384) ? 0 : 384) + (g << 7) + physo(o);
        g_gruT[kp * 768 + slot] = pack2(W[of * ND + 2 * kp], W[of * ND + 2 * kp + 1]);
    }
}

// P = nf @ W1a + b1 ; Q = nf @ W1b  (per node), 64 nodes/block
__global__ __launch_bounds__(512) void pq_kernel(const float* __restrict__ nf,
                                                 const float* __restrict__ b1) {
    __shared__ __align__(16) float sX[64][ND];
    const int t = threadIdx.x, w = t >> 5, lane = t & 31, o0 = lane * 4;
    const int n0 = blockIdx.x * 64;

    #pragma unroll
    for (int i = 0; i < 4; i++) {
        int n = w * 4 + i;
        ((float4*)sX[n])[lane] = ((const float4*)(nf + (size_t)(n0 + n) * ND))[lane];
    }
    __syncwarp();

    u64 aP[16], aQ[16];
    {
        float4 b1v = *(const float4*)(b1 + o0);
        float bb[4] = {b1v.x, b1v.y, b1v.z, b1v.w};
        #pragma unroll
        for (int i = 0; i < 4; i++)
            #pragma unroll
            for (int j = 0; j < 4; j++) {
                aP[4 * i + j] = pack2(bb[j], 0.f);
                aQ[4 * i + j] = 0ull;
            }
    }

    #pragma unroll 2
    for (int kp2 = 0; kp2 < 32; kp2++) {
        const u64* wp = g_w1p + (size_t)(2 * kp2) * ND;
        const u64* wq = g_w1p + (size_t)(64 + 2 * kp2) * ND;
        ulonglong2 pA = *(const ulonglong2*)(wp + 2 * lane);
        ulonglong2 pB = *(const ulonglong2*)(wp + 64 + 2 * lane);
        ulonglong2 pC = *(const ulonglong2*)(wp + ND + 2 * lane);
        ulonglong2 pD = *(const ulonglong2*)(wp + ND + 64 + 2 * lane);
        ulonglong2 qA = *(const ulonglong2*)(wq + 2 * lane);
        ulonglong2 qB = *(const ulonglong2*)(wq + 64 + 2 * lane);
        ulonglong2 qC = *(const ulonglong2*)(wq + ND + 2 * lane);
        ulonglong2 qD = *(const ulonglong2*)(wq + ND + 64 + 2 * lane);
        #pragma unroll
        for (int i = 0; i < 4; i++) {
            int n = w * 4 + i;
            ulonglong2 x = *(const ulonglong2*)&sX[n][4 * kp2];
            u64* p = aP + 4 * i;
            u64* q = aQ + 4 * i;
            ffma2(p[0], pA.x, x.x); ffma2(p[1], pA.y, x.x);
            ffma2(p[2], pB.x, x.x); ffma2(p[3], pB.y, x.x);
            ffma2(p[0], pC.x, x.y); ffma2(p[1], pC.y, x.y);
            ffma2(p[2], pD.x, x.y); ffma2(p[3], pD.y, x.y);
            ffma2(q[0], qA.x, x.x); ffma2(q[1], qA.y, x.x);
            ffma2(q[2], qB.x, x.x); ffma2(q[3], qB.y, x.x);
            ffma2(q[0], qC.x, x.y); ffma2(q[1], qC.y, x.y);
            ffma2(q[2], qD.x, x.y); ffma2(q[3], qD.y, x.y);
        }
    }
    #pragma unroll
    for (int i = 0; i < 4; i++) {
        int n = n0 + w * 4 + i;
        float4 pv, qv;
        float lo, hi;
        unpack2(aP[4 * i + 0], lo, hi); pv.x = lo + hi;
        unpack2(aP[4 * i + 1], lo, hi); pv.y = lo + hi;
        unpack2(aP[4 * i + 2], lo, hi); pv.z = lo + hi;
        unpack2(aP[4 * i + 3], lo, hi); pv.w = lo + hi;
        unpack2(aQ[4 * i + 0], lo, hi); qv.x = lo + hi;
        unpack2(aQ[4 * i + 1], lo, hi); qv.y = lo + hi;
        unpack2(aQ[4 * i + 2], lo, hi); qv.z = lo + hi;
        unpack2(aQ[4 * i + 3], lo, hi); qv.w = lo + hi;
        *(float4*)(g_P + (size_t)n * ND + o0) = pv;
        *(float4*)(g_Q + (size_t)n * ND + o0) = qv;
    }
}

// Edge kernel: R = ef@W1c, h = LN(P[src]+Q[dst]+R), msg = (relu(h)@W2+b2)*gate
__global__ __launch_bounds__(256, 1) void edge_kernel(
    const int* __restrict__ ei, const float* __restrict__ ef,
    const float* __restrict__ ln_g, const float* __restrict__ ln_b,
    const float* __restrict__ b2, const float* __restrict__ gate_w,
    const float* __restrict__ gate_b)
{
    extern __shared__ __align__(16) unsigned char smem_raw[];
    u64* sW1c = (u64*)smem_raw;                 // 32 kp x 128  (32 KB)
    u64* sW2  = sW1c + 32 * ND;                 // 64 kp x 128  (64 KB)
    float* ef_s = (float*)(sW2 + 64 * ND);      // 8 warps x 8 edges x 64 (16 KB)
    float* hs   = ef_s + 8 * EPW * ED;          // 8 warps x 8 edges x 128 (32 KB)

    const int t = threadIdx.x, w = t >> 5, lane = t & 31, o0 = lane * 4;

    // cooperative weight load into smem (layout already permuted in global)
    {
        const ulonglong2* s1 = (const ulonglong2*)(g_w1p + 128 * ND);
        ulonglong2* d1 = (ulonglong2*)sW1c;
        #pragma unroll
        for (int i = 0; i < 8; i++) d1[t + 256 * i] = s1[t + 256 * i];
        const ulonglong2* s2 = (const ulonglong2*)g_w2p;
        ulonglong2* d2 = (ulonglong2*)sW2;
        #pragma unroll
        for (int i = 0; i < 16; i++) d2[t + 256 * i] = s2[t + 256 * i];
    }
    const float gw0 = gate_w[lane], gw1 = gate_w[lane + 32], gb = gate_b[0];
    const float4 b2v = ((const float4*)b2)[lane];
    const float4 lgv = ((const float4*)ln_g)[lane];
    const float4 lbv = ((const float4*)ln_b)[lane];
    __syncthreads();

    float* efw = ef_s + w * EPW * ED;
    float* hsw = hs + w * EPW * ND;

    for (int it = 0; it < NT; it++) {
        const int e_base = (blockIdx.x * NT + it) * (8 * EPW) + w * EPW;
        int sReg = 0, dReg = 0;
        if (lane < EPW) {
            sReg = ei[e_base + lane];
            dReg = ei[N_EDGES + e_base + lane];
        }
        // load 8 edge-feature rows (64 f each): lanes cover 2 edges/pass
        #pragma unroll
        for (int pass = 0; pass < 4; pass++) {
            int e = pass * 2 + (lane >> 4);
            int idx = lane & 15;
            ((float4*)(efw + e * ED))[idx] =
                ((const float4*)(ef + (size_t)(e_base + e) * ED))[idx];
        }
        __syncwarp();

        // ---- R GEMM (K=64) ----
        u64 acc[32];
        #pragma unroll
        for (int i = 0; i < 32; i++) acc[i] = 0ull;
        #pragma unroll 2
        for (int kp2 = 0; kp2 < 16; kp2++) {
            const u64* wp = sW1c + (2 * kp2) * ND;
            ulonglong2 wA = *(const ulonglong2*)(wp + 2 * lane);
            ulonglong2 wB = *(const ulonglong2*)(wp + 64 + 2 * lane);
            ulonglong2 wC = *(const ulonglong2*)(wp + ND + 2 * lane);
            ulonglong2 wD = *(const ulonglong2*)(wp + ND + 64 + 2 * lane);
            #pragma unroll
            for (int e = 0; e < EPW; e++) {
                ulonglong2 x = *(const ulonglong2*)(efw + e * ED + 4 * kp2);
                u64* a = acc + 4 * e;
                ffma2(a[0], wA.x, x.x); ffma2(a[1], wA.y, x.x);
                ffma2(a[2], wB.x, x.x); ffma2(a[3], wB.y, x.x);
                ffma2(a[0], wC.x, x.y); ffma2(a[1], wC.y, x.y);
                ffma2(a[2], wD.x, x.y); ffma2(a[3], wD.y, x.y);
            }
        }

        // ---- add P[src] + Q[dst], LayerNorm, ReLU -> hs ----
        #pragma unroll
        for (int e = 0; e < EPW; e++) {
            int s = __shfl_sync(0xffffffffu, sReg, e);
            int d = __shfl_sync(0xffffffffu, dReg, e);
            float4 Pv = *(const float4*)(g_P + (size_t)s * ND + o0);
            float4 Qv = *(const float4*)(g_Q + (size_t)d * ND + o0);
            float v[4];
            float lo, hi;
            unpack2(acc[4 * e + 0], lo, hi); v[0] = lo + hi + Pv.x + Qv.x;
            unpack2(acc[4 * e + 1], lo, hi); v[1] = lo + hi + Pv.y + Qv.y;
            unpack2(acc[4 * e + 2], lo, hi); v[2] = lo + hi + Pv.z + Qv.z;
            unpack2(acc[4 * e + 3], lo, hi); v[3] = lo + hi + Pv.w + Qv.w;
            float sm = v[0] + v[1] + v[2] + v[3];
            float sq = v[0] * v[0] + v[1] * v[1] + v[2] * v[2] + v[3] * v[3];
            #pragma unroll
            for (int off = 16; off; off >>= 1) {
                sm += __shfl_xor_sync(0xffffffffu, sm, off);
                sq += __shfl_xor_sync(0xffffffffu, sq, off);
            }
            float mu  = sm * (1.0f / ND);
            float var = sq * (1.0f / ND) - mu * mu;
            float inv = rsqrtf(var + 1e-5f);
            float4 hv;
            hv.x = fmaxf((v[0] - mu) * inv * lgv.x + lbv.x, 0.f);
            hv.y = fmaxf((v[1] - mu) * inv * lgv.y + lbv.y, 0.f);
            hv.z = fmaxf((v[2] - mu) * inv * lgv.z + lbv.z, 0.f);
            hv.w = fmaxf((v[3] - mu) * inv * lgv.w + lbv.w, 0.f);
            ((float4*)(hsw + e * ND))[lane] = hv;
        }
        __syncwarp();

        // ---- sigmoid gate per edge ----
        float gv[EPW];
        #pragma unroll
        for (int e = 0; e < EPW; e++) {
            float p = efw[e * ED + lane] * gw0 + efw[e * ED + lane + 32] * gw1;
            #pragma unroll
            for (int off = 16; off; off >>= 1)
                p += __shfl_xor_sync(0xffffffffu, p, off);
            gv[e] = sigmoidf_(p + gb);
        }

        // ---- layer 2 GEMM (K=128) ----
        #pragma unroll
        for (int i = 0; i < 32; i++) acc[i] = 0ull;
        #pragma unroll 2
        for (int kp2 = 0; kp2 < 32; kp2++) {
            const u64* wp = sW2 + (2 * kp2) * ND;
            ulonglong2 wA = *(const ulonglong2*)(wp + 2 * lane);
            ulonglong2 wB = *(const ulonglong2*)(wp + 64 + 2 * lane);
            ulonglong2 wC = *(const ulonglong2*)(wp + ND + 2 * lane);
            ulonglong2 wD = *(const ulonglong2*)(wp + ND + 64 + 2 * lane);
            #pragma unroll
            for (int e = 0; e < EPW; e++) {
                ulonglong2 x = *(const ulonglong2*)(hsw + e * ND + 4 * kp2);
                u64* a = acc + 4 * e;
                ffma2(a[0], wA.x, x.x); ffma2(a[1], wA.y, x.x);
                ffma2(a[2], wB.x, x.x); ffma2(a[3], wB.y, x.x);
                ffma2(a[0], wC.x, x.y); ffma2(a[1], wC.y, x.y);
                ffma2(a[2], wD.x, x.y); ffma2(a[3], wD.y, x.y);
            }
        }

        // ---- bias + gate + vectorized scatter-add ----
        #pragma unroll
        for (int e = 0; e < EPW; e++) {
            int d = __shfl_sync(0xffffffffu, dReg, e);
            float* dp = g_agg + (size_t)d * ND + o0;
            float lo, hi, m0, m1, m2, m3;
            unpack2(acc[4 * e + 0], lo, hi); m0 = (lo + hi + b2v.x) * gv[e];
            unpack2(acc[4 * e + 1], lo, hi); m1 = (lo + hi + b2v.y) * gv[e];
            unpack2(acc[4 * e + 2], lo, hi); m2 = (lo + hi + b2v.z) * gv[e];
            unpack2(acc[4 * e + 3], lo, hi); m3 = (lo + hi + b2v.w) * gv[e];
            red_add_v4(dp, m0, m1, m2, m3);
        }
        __syncwarp();
    }
}

__global__ __launch_bounds__(512) void gru_kernel(
    const float* __restrict__ nf, const float* __restrict__ b_ih,
    const float* __restrict__ b_hh, float* __restrict__ out)
{
    __shared__ __align__(16) float sA[64][ND];
    __shared__ __align__(16) float sX[64][ND];
    const int t = threadIdx.x, w = t >> 5, lane = t & 31, o0 = lane * 4;
    const int n0 = blockIdx.x * 64;

    #pragma unroll
    for (int i = 0; i < 4; i++) {
        int n = w * 4 + i;
        ((float4*)sA[n])[lane] = ((const float4*)(g_agg + (size_t)(n0 + n) * ND))[lane];
        ((float4*)sX[n])[lane] = ((const float4*)(nf + (size_t)(n0 + n) * ND))[lane];
    }
    __syncwarp();

    float rv[16], zv[16];

    #pragma unroll
    for (int g = 0; g < 3; g++) {
        u64 gi[16], gh[16];
        {
            float4 biv = *(const float4*)(b_ih + g * ND + o0);
            float4 bhv = *(const float4*)(b_hh + g * ND + o0);
            float bi[4] = {biv.x, biv.y, biv.z, biv.w};
            float bh[4] = {bhv.x, bhv.y, bhv.z, bhv.w};
            #pragma unroll
            for (int i = 0; i < 4; i++)
                #pragma unroll
                for (int j = 0; j < 4; j++) {
                    gi[4 * i + j] = pack2(bi[j], 0.f);
                    gh[4 * i + j] = pack2(bh[j], 0.f);
                }
        }
        #pragma unroll 2
        for (int kp2 = 0; kp2 < 32; kp2++) {
            const u64* base0 = g_gruT + (size_t)(2 * kp2) * 768;
            const u64* base1 = base0 + 768;
            ulonglong2 iA = *(const ulonglong2*)(base0 + g * ND + 2 * lane);
            ulonglong2 iB = *(const ulonglong2*)(base0 + g * ND + 64 + 2 * lane);
            ulonglong2 iC = *(const ulonglong2*)(base1 + g * ND + 2 * lane);
            ulonglong2 iD = *(const ulonglong2*)(base1 + g * ND + 64 + 2 * lane);
            ulonglong2 hA = *(const ulonglong2*)(base0 + 384 + g * ND + 2 * lane);
            ulonglong2 hB = *(const ulonglong2*)(base0 + 384 + g * ND + 64 + 2 * lane);
            ulonglong2 hC = *(const ulonglong2*)(base1 + 384 + g * ND + 2 * lane);
            ulonglong2 hD = *(const ulonglong2*)(base1 + 384 + g * ND + 64 + 2 * lane);
            #pragma unroll
            for (int i = 0; i < 4; i++) {
                int n = w * 4 + i;
                ulonglong2 xa = *(const ulonglong2*)&sA[n][4 * kp2];
                ulonglong2 xx = *(const ulonglong2*)&sX[n][4 * kp2];
                u64* pi = gi + 4 * i;
                u64* ph = gh + 4 * i;
                ffma2(pi[0], iA.x, xa.x); ffma2(pi[1], iA.y, xa.x);
                ffma2(pi[2], iB.x, xa.x); ffma2(pi[3], iB.y, xa.x);
                ffma2(pi[0], iC.x, xa.y); ffma2(pi[1], iC.y, xa.y);
                ffma2(pi[2], iD.x, xa.y); ffma2(pi[3], iD.y, xa.y);
                ffma2(ph[0], hA.x, xx.x); ffma2(ph[1], hA.y, xx.x);
                ffma2(ph[2], hB.x, xx.x); ffma2(ph[3], hB.y, xx.x);
                ffma2(ph[0], hC.x, xx.y); ffma2(ph[1], hC.y, xx.y);
                ffma2(ph[2], hD.x, xx.y); ffma2(ph[3], hD.y, xx.y);
            }
        }
        #pragma unroll
        for (int i = 0; i < 4; i++) {
            int n = w * 4 + i;
            #pragma unroll
            for (int j = 0; j < 4; j++) {
                float il, ih, hl, hh;
                unpack2(gi[4 * i + j], il, ih);
                unpack2(gh[4 * i + j], hl, hh);
                float giv = il + ih, ghv = hl + hh;
                if (g == 0) {
                    rv[4 * i + j] = sigmoidf_(giv + ghv);
                } else if (g == 1) {
                    zv[4 * i + j] = sigmoidf_(giv + ghv);
                } else {
                    float nn = tanhf(giv + rv[4 * i + j] * ghv);
                    float x = sX[n][o0 + j];
                    float z = zv[4 * i + j];
                    rv[4 * i + j] = (1.0f - z) * nn + z * x;
                }
            }
        }
    }
    #pragma unroll
    for (int i = 0; i < 4; i++) {
        int n = n0 + w * 4 + i;
        float4 ov = make_float4(rv[4 * i], rv[4 * i + 1], rv[4 * i + 2], rv[4 * i + 3]);
        *(float4*)(out + (size_t)n * ND + o0) = ov;
    }
}

#define EDGE_SMEM (32 * 128 * 8 + 64 * 128 * 8 + 8 * EPW * ED * 4 + 8 * EPW * ND * 4)

extern "C" void kernel_launch(void* const* d_in, const int* in_sizes, int n_in,
                              void* d_out, int out_size) {
    const float* nf     = (const float*)d_in[0];
    const int*   ei     = (const int*)d_in[1];
    const float* ef     = (const float*)d_in[2];
    const float* W1     = (const float*)d_in[3];
    const float* b1     = (const float*)d_in[4];
    const float* ln_g   = (const float*)d_in[5];
    const float* ln_b   = (const float*)d_in[6];
    const float* W2     = (const float*)d_in[7];
    const float* b2     = (const float*)d_in[8];
    const float* gate_w = (const float*)d_in[9];
    const float* gate_b = (const float*)d_in[10];
    const float* W_ih   = (const float*)d_in[11];
    const float* b_ih   = (const float*)d_in[12];
    const float* W_hh   = (const float*)d_in[13];
    const float* b_hh   = (const float*)d_in[14];
    float* out = (float*)d_out;

    cudaFuncSetAttribute(edge_kernel, cudaFuncAttributeMaxDynamicSharedMemorySize,
                         EDGE_SMEM);

    zero_agg_kernel<<<592, 256>>>();
    prep_kernel<<<192, 256>>>(W1, W2, W_ih, W_hh);
    pq_kernel<<<N_NODES / 64, 512>>>(nf, b1);
    edge_kernel<<<N_EDGES / (8 * EPW * NT), 256, EDGE_SMEM>>>(
        ei, ef, ln_g, ln_b, b2, gate_w, gate_b);
    gru_kernel<<<N_NODES / 64, 512>>>(nf, b_ih, b_hh, out);
}